// round 7
// baseline (speedup 1.0000x reference)
#include <cuda_runtime.h>
#include <cuda_fp16.h>
#include <cuda_bf16.h>

// GraphSAGE 3-layer, mean aggregator, N=100000, E=1600000, F=64.
// R7: aggregate restructured to kill the csr->gather latency chain:
//     lane-parallel index load + shfl distribution + 8-deep independent
//     gather batches (MLP ~8 vs ~2 before). fp16 gather kept (bytes become
//     binding once latency is hidden). Rest unchanged from R6.

#define F 64
#define NMAX 100000
#define EMAX 1600000
#define SCAN_BS 512

__device__ int   g_counts[NMAX];
__device__ int   g_cursor[NMAX];
__device__ int   g_row_off[NMAX + 1];
__device__ int   g_partials[256];
__device__ int   g_poff[256];
__device__ int   g_total;
__device__ int   g_csr[EMAX];
__device__ __align__(16) float  g_bufA[(size_t)NMAX * F];
__device__ __align__(16) float  g_bufB[(size_t)NMAX * F];
__device__ __align__(16) float  g_agg [(size_t)NMAX * F];
__device__ __align__(16) __half g_h16 [(size_t)NMAX * F];

// ---------------------------------------------------------------- CSR build

__global__ void k_hist(const int* __restrict__ dst, int e) {
    int i = blockIdx.x * blockDim.x + threadIdx.x;
    if (i < e) atomicAdd(&g_counts[dst[i]], 1);
}

__global__ void k_scan_blocks(int n) {
    int i = blockIdx.x * SCAN_BS + threadIdx.x;
    int v = (i < n) ? g_counts[i] : 0;
    int lane = threadIdx.x & 31, wid = threadIdx.x >> 5;

    int incl = v;
    #pragma unroll
    for (int o = 1; o < 32; o <<= 1) {
        int x = __shfl_up_sync(0xffffffffu, incl, o);
        if (lane >= o) incl += x;
    }
    __shared__ int ws[16];
    if (lane == 31) ws[wid] = incl;
    __syncthreads();
    if (wid == 0) {
        int s = (lane < 16) ? ws[lane] : 0;
        #pragma unroll
        for (int o = 1; o < 16; o <<= 1) {
            int x = __shfl_up_sync(0xffffffffu, s, o);
            if (lane >= o) s += x;
        }
        if (lane < 16) ws[lane] = s;
    }
    __syncthreads();
    int excl = incl - v + (wid ? ws[wid - 1] : 0);
    if (i < n) g_cursor[i] = excl;
    if (threadIdx.x == SCAN_BS - 1) g_partials[blockIdx.x] = ws[15];
}

__global__ void k_scan_partials(int nb) {
    int t = threadIdx.x;
    int lane = t & 31, wid = t >> 5;
    int v = (t < nb) ? g_partials[t] : 0;
    int incl = v;
    #pragma unroll
    for (int o = 1; o < 32; o <<= 1) {
        int x = __shfl_up_sync(0xffffffffu, incl, o);
        if (lane >= o) incl += x;
    }
    __shared__ int ws[8];
    if (lane == 31) ws[wid] = incl;
    __syncthreads();
    if (wid == 0) {
        int s = (lane < 8) ? ws[lane] : 0;
        #pragma unroll
        for (int o = 1; o < 8; o <<= 1) {
            int x = __shfl_up_sync(0xffffffffu, s, o);
            if (lane >= o) s += x;
        }
        if (lane < 8) ws[lane] = s;
    }
    __syncthreads();
    incl += (wid ? ws[wid - 1] : 0);
    g_poff[t] = incl - v;
    if (t == 255) g_total = incl;
}

__global__ void k_scan_finalize(int n) {
    int i = blockIdx.x * SCAN_BS + threadIdx.x;
    if (i < n) {
        int off = g_cursor[i] + g_poff[i >> 9];
        g_row_off[i] = off;
        g_cursor[i]  = off;
        if (i == n - 1) g_row_off[n] = g_total;
    }
}

__global__ void k_scatter(const int* __restrict__ src, const int* __restrict__ dst, int e) {
    int i = blockIdx.x * blockDim.x + threadIdx.x;
    if (i < e) {
        int p = atomicAdd(&g_cursor[dst[i]], 1);
        g_csr[p] = src[i];
    }
}

// ---------------------------------------------------------------- fp16 shadow

__global__ void k_tofp16(const float* __restrict__ in, int n2) {
    int i = blockIdx.x * blockDim.x + threadIdx.x;
    if (i < n2) {
        float2 v = ((const float2*)in)[i];
        ((__half2*)g_h16)[i] = __float22half2_rn(v);
    }
}

// ---------------------------------------------------------------- aggregate

// One warp per node. Lane l owns features [2l, 2l+1].
// Indices for up to 32 edges loaded lane-parallel (one coalesced LDG),
// distributed by shfl, gathers issued in independent batches of 8.
__global__ void k_aggregate(int n) {
    int gtid = blockIdx.x * blockDim.x + threadIdx.x;
    int node = gtid >> 5;
    int lane = gtid & 31;
    if (node >= n) return;

    int beg = g_row_off[node];
    int end = g_row_off[node + 1];
    const __half2* hp = (const __half2*)g_h16;

    float ax = 0.f, ay = 0.f;
    for (int base = beg; base < end; base += 32) {
        int m = end - base;
        if (m > 32) m = 32;
        int idx = (lane < m) ? g_csr[base + lane] : 0;

        int j = 0;
        for (; j + 8 <= m; j += 8) {
            int s[8];
            #pragma unroll
            for (int k = 0; k < 8; k++)
                s[k] = __shfl_sync(0xffffffffu, idx, j + k);
            float2 v[8];
            #pragma unroll
            for (int k = 0; k < 8; k++)
                v[k] = __half22float2(hp[(size_t)s[k] * 32 + lane]);
            #pragma unroll
            for (int k = 0; k < 8; k++) {
                ax += v[k].x;
                ay += v[k].y;
            }
        }
        // remainder (<8): still batch loads before accumulating
        int rem = m - j;
        if (rem > 0) {
            int s[7];
            float2 v[7];
            #pragma unroll
            for (int k = 0; k < 7; k++) {
                if (k < rem) s[k] = __shfl_sync(0xffffffffu, idx, j + k);
            }
            #pragma unroll
            for (int k = 0; k < 7; k++) {
                if (k < rem) v[k] = __half22float2(hp[(size_t)s[k] * 32 + lane]);
            }
            #pragma unroll
            for (int k = 0; k < 7; k++) {
                if (k < rem) {
                    ax += v[k].x;
                    ay += v[k].y;
                }
            }
        }
    }

    int deg = end - beg;
    float inv = 1.f / (float)(deg > 0 ? deg : 1);
    float2 r;
    r.x = ax * inv;
    r.y = ay * inv;
    ((float2*)g_agg)[(size_t)node * 32 + lane] = r;
}

// ---------------------------------------------------------------- transform

// Packed dual-FMA helpers (Blackwell f32x2 pipe)
__device__ __forceinline__ void ffma2(unsigned long long& acc,
                                      unsigned long long a,
                                      unsigned long long b) {
    asm("fma.rn.f32x2 %0, %1, %2, %0;" : "+l"(acc) : "l"(a), "l"(b));
}
__device__ __forceinline__ unsigned long long pack2(float h) {
    unsigned long long r;
    asm("mov.b64 %0, {%1, %1};" : "=l"(r) : "f"(h));
    return r;
}
__device__ __forceinline__ void unpack2(unsigned long long p, float& lo, float& hi) {
    asm("mov.b64 {%0, %1}, %2;" : "=f"(lo), "=f"(hi) : "l"(p));
}

__device__ __forceinline__ void mac_row2(const float* __restrict__ row,
                                         const float* __restrict__ Wt,
                                         unsigned long long acc[F / 2]) {
    for (int k0 = 0; k0 < F; k0 += 4) {
        float4 hv = ((const float4*)row)[k0 >> 2];
        float hk[4] = {hv.x, hv.y, hv.z, hv.w};
        #pragma unroll
        for (int kk = 0; kk < 4; kk++) {
            unsigned long long hh = pack2(hk[kk]);
            const ulonglong2* wr = (const ulonglong2*)&Wt[(k0 + kk) * F];
            #pragma unroll
            for (int j = 0; j < 16; j++) {
                ulonglong2 w = wr[j];
                ffma2(acc[2 * j + 0], hh, w.x);
                ffma2(acc[2 * j + 1], hh, w.y);
            }
        }
    }
}

__global__ void k_transform(const float* __restrict__ h,
                            const float* __restrict__ agg,
                            const float* __restrict__ Ws,
                            const float* __restrict__ Wn,
                            const float* __restrict__ b,
                            float* __restrict__ out,
                            int n, int leaky, int write16) {
    __shared__ __align__(16) float Wts[F * F];
    __shared__ __align__(16) float Wtn[F * F];
    __shared__ __align__(16) float sb[F];

    int t = threadIdx.x;
    for (int i = t; i < F * F; i += blockDim.x) {
        int j = i >> 6, k = i & 63;
        Wts[k * F + j] = Ws[i];
        Wtn[k * F + j] = Wn[i];
    }
    if (t < F) sb[t] = b[t];
    __syncthreads();

    int node = blockIdx.x * blockDim.x + t;
    if (node >= n) return;

    unsigned long long acc[F / 2];
    const unsigned long long* bp = (const unsigned long long*)sb;
    #pragma unroll
    for (int j = 0; j < F / 2; j++) acc[j] = bp[j];

    mac_row2(h   + (size_t)node * F, Wts, acc);
    mac_row2(agg + (size_t)node * F, Wtn, acc);

    float4*  o   = (float4*)(out + (size_t)node * F);
    __half2* o16 = ((__half2*)g_h16) + (size_t)node * 32;
    #pragma unroll
    for (int j4 = 0; j4 < 16; j4++) {
        float a0, a1, a2, a3;
        unpack2(acc[2 * j4 + 0], a0, a1);
        unpack2(acc[2 * j4 + 1], a2, a3);
        float4 v;
        if (leaky) {
            v.x = a0 >= 0.f ? a0 : 0.01f * a0;
            v.y = a1 >= 0.f ? a1 : 0.01f * a1;
            v.z = a2 >= 0.f ? a2 : 0.01f * a2;
            v.w = a3 >= 0.f ? a3 : 0.01f * a3;
        } else {
            v.x = a0; v.y = a1; v.z = a2; v.w = a3;
        }
        o[j4] = v;
        if (write16) {
            o16[2 * j4 + 0] = __float22half2_rn(make_float2(v.x, v.y));
            o16[2 * j4 + 1] = __float22half2_rn(make_float2(v.z, v.w));
        }
    }
}

// ---------------------------------------------------------------- launch

extern "C" void kernel_launch(void* const* d_in, const int* in_sizes, int n_in,
                              void* d_out, int out_size) {
    const float* in_feat = (const float*)d_in[0];
    const int*   src     = (const int*)d_in[1];
    const int*   dst     = (const int*)d_in[2];
    const float* w_self1 = (const float*)d_in[3];
    const float* w_nei1  = (const float*)d_in[4];
    const float* b1      = (const float*)d_in[5];
    const float* w_self2 = (const float*)d_in[6];
    const float* w_nei2  = (const float*)d_in[7];
    const float* b2      = (const float*)d_in[8];
    const float* w_self3 = (const float*)d_in[9];
    const float* w_nei3  = (const float*)d_in[10];
    const float* b3      = (const float*)d_in[11];
    float* out = (float*)d_out;

    int n = in_sizes[0] / F;     // 100000
    int e = in_sizes[1];         // 1600000
    int nscan = (n + SCAN_BS - 1) / SCAN_BS;

    float *bufA, *bufB, *agg;
    int* counts;
    cudaGetSymbolAddress((void**)&bufA, g_bufA);
    cudaGetSymbolAddress((void**)&bufB, g_bufB);
    cudaGetSymbolAddress((void**)&agg,  g_agg);
    cudaGetSymbolAddress((void**)&counts, g_counts);

    // ---- CSR build (once per launch) ----
    cudaMemsetAsync(counts, 0, (size_t)n * sizeof(int));
    k_hist<<<(e + 255) / 256, 256>>>(dst, e);
    k_scan_blocks<<<nscan, SCAN_BS>>>(n);
    k_scan_partials<<<1, 256>>>(nscan);
    k_scan_finalize<<<nscan, SCAN_BS>>>(n);
    k_scatter<<<(e + 255) / 256, 256>>>(src, dst, e);

    // fp16 shadow of the input features
    int n2 = n * F / 2;
    k_tofp16<<<(n2 + 255) / 256, 256>>>(in_feat, n2);

    int agg_grid = (n * 32 + 255) / 256;   // warp per node
    int tr_grid  = (n + 255) / 256;

    // ---- layer 1 ----
    k_aggregate<<<agg_grid, 256>>>(n);
    k_transform<<<tr_grid, 256>>>(in_feat, agg, w_self1, w_nei1, b1, bufA, n, 1, 1);
    // ---- layer 2 ----
    k_aggregate<<<agg_grid, 256>>>(n);
    k_transform<<<tr_grid, 256>>>(bufA, agg, w_self2, w_nei2, b2, bufB, n, 1, 1);
    // ---- layer 3 ----
    k_aggregate<<<agg_grid, 256>>>(n);
    k_transform<<<tr_grid, 256>>>(bufB, agg, w_self3, w_nei3, b3, out, n, 0, 0);
}

// round 8
// speedup vs baseline: 1.1716x; 1.1716x over previous
#include <cuda_runtime.h>
#include <cuda_bf16.h>

// GraphSAGE 3-layer, mean aggregator, N=100000, E=1600000, F=64.
// R8: revert to R2 gather (fp32 simple — best measured); single-kernel
//     decoupled-lookback scan (fewer launches; also places k_aggregate at
//     profiled launch index 3); aggregate inner loop unrolled 8-deep scalar.

#define F 64
#define NMAX 100000
#define EMAX 1600000
#define SCAN_BS 512

__device__ int   g_counts[NMAX];
__device__ int   g_cursor[NMAX];
__device__ int   g_row_off[NMAX + 1];
__device__ unsigned long long g_scan_state[256];   // (status<<32)|value
__device__ int   g_csr[EMAX];
__device__ __align__(16) float g_bufA[(size_t)NMAX * F];
__device__ __align__(16) float g_bufB[(size_t)NMAX * F];
__device__ __align__(16) float g_agg [(size_t)NMAX * F];

// ---------------------------------------------------------------- CSR build

__global__ void k_hist(const int* __restrict__ dst, int e) {
    int i = blockIdx.x * blockDim.x + threadIdx.x;
    if (i < e) atomicAdd(&g_counts[dst[i]], 1);
}

// Single-pass decoupled-lookback scan: counts -> row_off (+cursor).
// status: 0=invalid, 1=aggregate ready, 2=prefix ready (value in low 32 bits).
__global__ void k_scan_lookback(int n) {
    int bid = blockIdx.x;
    int t = threadIdx.x;
    int i = bid * SCAN_BS + t;
    int v = (i < n) ? g_counts[i] : 0;
    int lane = t & 31, wid = t >> 5;

    int incl = v;
    #pragma unroll
    for (int o = 1; o < 32; o <<= 1) {
        int x = __shfl_up_sync(0xffffffffu, incl, o);
        if (lane >= o) incl += x;
    }
    __shared__ int ws[16];
    if (lane == 31) ws[wid] = incl;
    __syncthreads();
    if (wid == 0) {
        int s = (lane < 16) ? ws[lane] : 0;
        #pragma unroll
        for (int o = 1; o < 16; o <<= 1) {
            int x = __shfl_up_sync(0xffffffffu, s, o);
            if (lane >= o) s += x;
        }
        if (lane < 16) ws[lane] = s;
    }
    __syncthreads();
    int excl_local = incl - v + (wid ? ws[wid - 1] : 0);
    int block_total = ws[15];

    __shared__ int s_exclpref;
    if (wid == 0) {
        if (bid == 0) {
            if (lane == 0) {
                atomicExch(&g_scan_state[0],
                           ((unsigned long long)2 << 32) | (unsigned)block_total);
                s_exclpref = 0;
            }
        } else {
            if (lane == 0)
                atomicExch(&g_scan_state[bid],
                           ((unsigned long long)1 << 32) | (unsigned)block_total);
            // windowed parallel lookback (warp 0)
            int excl = 0;
            int lb = bid - 1;
            while (true) {
                int idx = lb - lane;
                unsigned long long s = (idx >= 0)
                    ? *(volatile unsigned long long*)&g_scan_state[idx]
                    : ((unsigned long long)2 << 32);
                int st = (int)(s >> 32);
                if (__all_sync(0xffffffffu, st != 0)) {
                    unsigned pre = __ballot_sync(0xffffffffu, st == 2);
                    unsigned val = (unsigned)s;
                    if (pre) {
                        int fp = __ffs(pre) - 1;          // nearest prefix
                        int c = (lane <= fp) ? (int)val : 0;
                        #pragma unroll
                        for (int o = 16; o; o >>= 1)
                            c += __shfl_down_sync(0xffffffffu, c, o);
                        excl += __shfl_sync(0xffffffffu, c, 0);
                        break;
                    } else {
                        int c = (int)val;
                        #pragma unroll
                        for (int o = 16; o; o >>= 1)
                            c += __shfl_down_sync(0xffffffffu, c, o);
                        excl += __shfl_sync(0xffffffffu, c, 0);
                        lb -= 32;
                    }
                }
            }
            if (lane == 0) {
                atomicExch(&g_scan_state[bid],
                           ((unsigned long long)2 << 32) | (unsigned)(excl + block_total));
                s_exclpref = excl;
            }
        }
    }
    __syncthreads();
    int off = excl_local + s_exclpref;
    if (i < n) {
        g_row_off[i] = off;
        g_cursor[i]  = off;
        if (i == n - 1) g_row_off[n] = off + v;
    }
}

__global__ void k_scatter(const int* __restrict__ src, const int* __restrict__ dst, int e) {
    int i = blockIdx.x * blockDim.x + threadIdx.x;
    if (i < e) {
        int p = atomicAdd(&g_cursor[dst[i]], 1);
        g_csr[p] = src[i];
    }
}

// ---------------------------------------------------------------- aggregate

// One warp per node. Lane l owns features [2l, 2l+1] (float2). 8-deep unroll.
__global__ void k_aggregate(const float* __restrict__ h, int n) {
    int gtid = blockIdx.x * blockDim.x + threadIdx.x;
    int node = gtid >> 5;
    int lane = gtid & 31;
    if (node >= n) return;

    int beg = g_row_off[node];
    int end = g_row_off[node + 1];
    const float2* hp = (const float2*)h;

    float ax = 0.f, ay = 0.f;
    int e = beg;
    for (; e + 8 <= end; e += 8) {
        int s0 = g_csr[e + 0];
        int s1 = g_csr[e + 1];
        int s2 = g_csr[e + 2];
        int s3 = g_csr[e + 3];
        int s4 = g_csr[e + 4];
        int s5 = g_csr[e + 5];
        int s6 = g_csr[e + 6];
        int s7 = g_csr[e + 7];
        float2 v0 = hp[(size_t)s0 * 32 + lane];
        float2 v1 = hp[(size_t)s1 * 32 + lane];
        float2 v2 = hp[(size_t)s2 * 32 + lane];
        float2 v3 = hp[(size_t)s3 * 32 + lane];
        float2 v4 = hp[(size_t)s4 * 32 + lane];
        float2 v5 = hp[(size_t)s5 * 32 + lane];
        float2 v6 = hp[(size_t)s6 * 32 + lane];
        float2 v7 = hp[(size_t)s7 * 32 + lane];
        ax += ((v0.x + v1.x) + (v2.x + v3.x)) + ((v4.x + v5.x) + (v6.x + v7.x));
        ay += ((v0.y + v1.y) + (v2.y + v3.y)) + ((v4.y + v5.y) + (v6.y + v7.y));
    }
    for (; e < end; e++) {
        float2 v = hp[(size_t)g_csr[e] * 32 + lane];
        ax += v.x;
        ay += v.y;
    }
    int deg = end - beg;
    float inv = 1.f / (float)(deg > 0 ? deg : 1);
    float2 r;
    r.x = ax * inv;
    r.y = ay * inv;
    ((float2*)g_agg)[(size_t)node * 32 + lane] = r;
}

// ---------------------------------------------------------------- transform

__device__ __forceinline__ void ffma2(unsigned long long& acc,
                                      unsigned long long a,
                                      unsigned long long b) {
    asm("fma.rn.f32x2 %0, %1, %2, %0;" : "+l"(acc) : "l"(a), "l"(b));
}
__device__ __forceinline__ unsigned long long pack2(float h) {
    unsigned long long r;
    asm("mov.b64 %0, {%1, %1};" : "=l"(r) : "f"(h));
    return r;
}
__device__ __forceinline__ void unpack2(unsigned long long p, float& lo, float& hi) {
    asm("mov.b64 {%0, %1}, %2;" : "=f"(lo), "=f"(hi) : "l"(p));
}

__device__ __forceinline__ void mac_row2(const float* __restrict__ row,
                                         const float* __restrict__ Wt,
                                         unsigned long long acc[F / 2]) {
    for (int k0 = 0; k0 < F; k0 += 4) {
        float4 hv = ((const float4*)row)[k0 >> 2];
        float hk[4] = {hv.x, hv.y, hv.z, hv.w};
        #pragma unroll
        for (int kk = 0; kk < 4; kk++) {
            unsigned long long hh = pack2(hk[kk]);
            const ulonglong2* wr = (const ulonglong2*)&Wt[(k0 + kk) * F];
            #pragma unroll
            for (int j = 0; j < 16; j++) {
                ulonglong2 w = wr[j];
                ffma2(acc[2 * j + 0], hh, w.x);
                ffma2(acc[2 * j + 1], hh, w.y);
            }
        }
    }
}

__global__ void k_transform(const float* __restrict__ h,
                            const float* __restrict__ agg,
                            const float* __restrict__ Ws,
                            const float* __restrict__ Wn,
                            const float* __restrict__ b,
                            float* __restrict__ out,
                            int n, int leaky) {
    __shared__ __align__(16) float Wts[F * F];
    __shared__ __align__(16) float Wtn[F * F];
    __shared__ __align__(16) float sb[F];

    int t = threadIdx.x;
    for (int i = t; i < F * F; i += blockDim.x) {
        int j = i >> 6, k = i & 63;
        Wts[k * F + j] = Ws[i];
        Wtn[k * F + j] = Wn[i];
    }
    if (t < F) sb[t] = b[t];
    __syncthreads();

    int node = blockIdx.x * blockDim.x + t;
    if (node >= n) return;

    unsigned long long acc[F / 2];
    const unsigned long long* bp = (const unsigned long long*)sb;
    #pragma unroll
    for (int j = 0; j < F / 2; j++) acc[j] = bp[j];

    mac_row2(h   + (size_t)node * F, Wts, acc);
    mac_row2(agg + (size_t)node * F, Wtn, acc);

    float4* o = (float4*)(out + (size_t)node * F);
    #pragma unroll
    for (int j4 = 0; j4 < 16; j4++) {
        float a0, a1, a2, a3;
        unpack2(acc[2 * j4 + 0], a0, a1);
        unpack2(acc[2 * j4 + 1], a2, a3);
        float4 v;
        if (leaky) {
            v.x = a0 >= 0.f ? a0 : 0.01f * a0;
            v.y = a1 >= 0.f ? a1 : 0.01f * a1;
            v.z = a2 >= 0.f ? a2 : 0.01f * a2;
            v.w = a3 >= 0.f ? a3 : 0.01f * a3;
        } else {
            v.x = a0; v.y = a1; v.z = a2; v.w = a3;
        }
        o[j4] = v;
    }
}

// ---------------------------------------------------------------- launch

extern "C" void kernel_launch(void* const* d_in, const int* in_sizes, int n_in,
                              void* d_out, int out_size) {
    const float* in_feat = (const float*)d_in[0];
    const int*   src     = (const int*)d_in[1];
    const int*   dst     = (const int*)d_in[2];
    const float* w_self1 = (const float*)d_in[3];
    const float* w_nei1  = (const float*)d_in[4];
    const float* b1      = (const float*)d_in[5];
    const float* w_self2 = (const float*)d_in[6];
    const float* w_nei2  = (const float*)d_in[7];
    const float* b2      = (const float*)d_in[8];
    const float* w_self3 = (const float*)d_in[9];
    const float* w_nei3  = (const float*)d_in[10];
    const float* b3      = (const float*)d_in[11];
    float* out = (float*)d_out;

    int n = in_sizes[0] / F;     // 100000
    int e = in_sizes[1];         // 1600000
    int nscan = (n + SCAN_BS - 1) / SCAN_BS;   // 196

    float *bufA, *bufB, *agg;
    int* counts;
    unsigned long long* sstate;
    cudaGetSymbolAddress((void**)&bufA, g_bufA);
    cudaGetSymbolAddress((void**)&bufB, g_bufB);
    cudaGetSymbolAddress((void**)&agg,  g_agg);
    cudaGetSymbolAddress((void**)&counts, g_counts);
    cudaGetSymbolAddress((void**)&sstate, g_scan_state);

    // ---- CSR build (once per launch) ----
    cudaMemsetAsync(counts, 0, (size_t)n * sizeof(int));
    cudaMemsetAsync(sstate, 0, (size_t)nscan * sizeof(unsigned long long));
    k_hist<<<(e + 255) / 256, 256>>>(dst, e);                 // launch 0
    k_scan_lookback<<<nscan, SCAN_BS>>>(n);                    // launch 1
    k_scatter<<<(e + 255) / 256, 256>>>(src, dst, e);          // launch 2

    int agg_grid = (n * 32 + 255) / 256;   // warp per node
    int tr_grid  = (n + 255) / 256;

    // ---- layer 1 ----
    k_aggregate<<<agg_grid, 256>>>(in_feat, n);                // launch 3 (profiled)
    k_transform<<<tr_grid, 256>>>(in_feat, agg, w_self1, w_nei1, b1, bufA, n, 1);
    // ---- layer 2 ----
    k_aggregate<<<agg_grid, 256>>>(bufA, n);
    k_transform<<<tr_grid, 256>>>(bufA, agg, w_self2, w_nei2, b2, bufB, n, 1);
    // ---- layer 3 ----
    k_aggregate<<<agg_grid, 256>>>(bufB, n);
    k_transform<<<tr_grid, 256>>>(bufB, agg, w_self3, w_nei3, b3, out, n, 0);
}

// round 11
// speedup vs baseline: 1.8648x; 1.5917x over previous
#include <cuda_runtime.h>
#include <cuda_fp16.h>
#include <cstdint>

// GraphSAGE 3-layer, mean agg, N=100000, E=1600000, F=64.
// R11 (= R10 resubmit; prior bench was an infra failure). Harness targets
// plain sm_100 -> tcgen05 unavailable; transform uses classic
// mma.sync.m16n8k16 (HMMA): D[128,64] = [h|agg](fp16) @ [Ws|Wn]^T(fp16),
// fp32 accumulate. CSR + aggregate unchanged from R8 (best: 407us).
// Staging loops widened to float4 granules.

#define F 64
#define NMAX 100000
#define EMAX 1600000
#define SCAN_BS 512
#define PADK 136          // half-elements per smem row (conflict-free)

__device__ int g_counts[NMAX];
__device__ int g_cursor[NMAX];
__device__ int g_row_off[NMAX + 1];
__device__ unsigned long long g_scan_state[256];
__device__ int g_csr[EMAX];
__device__ __align__(16) float g_bufA[(size_t)NMAX * F];
__device__ __align__(16) float g_bufB[(size_t)NMAX * F];
__device__ __align__(16) float g_agg [(size_t)NMAX * F];

// ---------------------------------------------------------------- CSR build

__global__ void k_hist(const int* __restrict__ dst, int e) {
    if (blockIdx.x == 0 && threadIdx.x < 256) g_scan_state[threadIdx.x] = 0;
    int i = blockIdx.x * blockDim.x + threadIdx.x;
    if (i < e) atomicAdd(&g_counts[dst[i]], 1);
}

__global__ void k_scan_lookback(int n) {
    int bid = blockIdx.x;
    int t = threadIdx.x;
    int i = bid * SCAN_BS + t;
    int v = (i < n) ? g_counts[i] : 0;
    int lane = t & 31, wid = t >> 5;

    int incl = v;
    #pragma unroll
    for (int o = 1; o < 32; o <<= 1) {
        int x = __shfl_up_sync(0xffffffffu, incl, o);
        if (lane >= o) incl += x;
    }
    __shared__ int ws[16];
    if (lane == 31) ws[wid] = incl;
    __syncthreads();
    if (wid == 0) {
        int s = (lane < 16) ? ws[lane] : 0;
        #pragma unroll
        for (int o = 1; o < 16; o <<= 1) {
            int x = __shfl_up_sync(0xffffffffu, s, o);
            if (lane >= o) s += x;
        }
        if (lane < 16) ws[lane] = s;
    }
    __syncthreads();
    int excl_local = incl - v + (wid ? ws[wid - 1] : 0);
    int block_total = ws[15];

    __shared__ int s_exclpref;
    if (wid == 0) {
        if (bid == 0) {
            if (lane == 0) {
                atomicExch(&g_scan_state[0],
                           ((unsigned long long)2 << 32) | (unsigned)block_total);
                s_exclpref = 0;
            }
        } else {
            if (lane == 0)
                atomicExch(&g_scan_state[bid],
                           ((unsigned long long)1 << 32) | (unsigned)block_total);
            int excl = 0;
            int lb = bid - 1;
            while (true) {
                int idx = lb - lane;
                unsigned long long s = (idx >= 0)
                    ? *(volatile unsigned long long*)&g_scan_state[idx]
                    : ((unsigned long long)2 << 32);
                int st = (int)(s >> 32);
                if (__all_sync(0xffffffffu, st != 0)) {
                    unsigned pre = __ballot_sync(0xffffffffu, st == 2);
                    unsigned val = (unsigned)s;
                    if (pre) {
                        int fp = __ffs(pre) - 1;
                        int c = (lane <= fp) ? (int)val : 0;
                        #pragma unroll
                        for (int o = 16; o; o >>= 1)
                            c += __shfl_down_sync(0xffffffffu, c, o);
                        excl += __shfl_sync(0xffffffffu, c, 0);
                        break;
                    } else {
                        int c = (int)val;
                        #pragma unroll
                        for (int o = 16; o; o >>= 1)
                            c += __shfl_down_sync(0xffffffffu, c, o);
                        excl += __shfl_sync(0xffffffffu, c, 0);
                        lb -= 32;
                    }
                }
            }
            if (lane == 0) {
                atomicExch(&g_scan_state[bid],
                           ((unsigned long long)2 << 32) | (unsigned)(excl + block_total));
                s_exclpref = excl;
            }
        }
    }
    __syncthreads();
    int off = excl_local + s_exclpref;
    if (i < n) {
        g_row_off[i] = off;
        g_cursor[i]  = off;
        if (i == n - 1) g_row_off[n] = off + v;
    }
}

__global__ void k_scatter(const int* __restrict__ src, const int* __restrict__ dst, int e) {
    int i = blockIdx.x * blockDim.x + threadIdx.x;
    if (i < e) {
        int p = atomicAdd(&g_cursor[dst[i]], 1);
        g_csr[p] = src[i];
    }
}

// ---------------------------------------------------------------- aggregate

// One warp per node. Lane l owns features [2l, 2l+1] (float2). 8-deep unroll.
__global__ void k_aggregate(const float* __restrict__ h, int n) {
    int gtid = blockIdx.x * blockDim.x + threadIdx.x;
    int node = gtid >> 5;
    int lane = gtid & 31;
    if (node >= n) return;

    int beg = g_row_off[node];
    int end = g_row_off[node + 1];
    const float2* hp = (const float2*)h;

    float ax = 0.f, ay = 0.f;
    int e = beg;
    for (; e + 8 <= end; e += 8) {
        int s0 = g_csr[e + 0], s1 = g_csr[e + 1], s2 = g_csr[e + 2], s3 = g_csr[e + 3];
        int s4 = g_csr[e + 4], s5 = g_csr[e + 5], s6 = g_csr[e + 6], s7 = g_csr[e + 7];
        float2 v0 = hp[(size_t)s0 * 32 + lane];
        float2 v1 = hp[(size_t)s1 * 32 + lane];
        float2 v2 = hp[(size_t)s2 * 32 + lane];
        float2 v3 = hp[(size_t)s3 * 32 + lane];
        float2 v4 = hp[(size_t)s4 * 32 + lane];
        float2 v5 = hp[(size_t)s5 * 32 + lane];
        float2 v6 = hp[(size_t)s6 * 32 + lane];
        float2 v7 = hp[(size_t)s7 * 32 + lane];
        ax += ((v0.x + v1.x) + (v2.x + v3.x)) + ((v4.x + v5.x) + (v6.x + v7.x));
        ay += ((v0.y + v1.y) + (v2.y + v3.y)) + ((v4.y + v5.y) + (v6.y + v7.y));
    }
    for (; e < end; e++) {
        float2 v = hp[(size_t)g_csr[e] * 32 + lane];
        ax += v.x;
        ay += v.y;
    }
    int deg = end - beg;
    float inv = 1.f / (float)(deg > 0 ? deg : 1);
    float2 r;
    r.x = ax * inv;
    r.y = ay * inv;
    ((float2*)g_agg)[(size_t)node * 32 + lane] = r;
}

// ---------------------------------------------------------------- transform

__device__ __forceinline__ void mma16816(float* d, const uint32_t* a,
                                         uint32_t b0, uint32_t b1) {
    asm volatile(
        "mma.sync.aligned.m16n8k16.row.col.f32.f16.f16.f32 "
        "{%0,%1,%2,%3}, {%4,%5,%6,%7}, {%8,%9}, {%0,%1,%2,%3};"
        : "+f"(d[0]), "+f"(d[1]), "+f"(d[2]), "+f"(d[3])
        : "r"(a[0]), "r"(a[1]), "r"(a[2]), "r"(a[3]), "r"(b0), "r"(b1));
}

// Per block: 128 nodes. sA[128][PADK] = [h | agg] fp16, sB[64][PADK] = [Ws|Wn] fp16.
// Warp w computes rows [32w, 32w+32) x all 64 cols via m16n8k16 fragments.
__global__ void __launch_bounds__(128) k_transform(const float* __restrict__ h,
                                                   const float* __restrict__ agg,
                                                   const float* __restrict__ Ws,
                                                   const float* __restrict__ Wn,
                                                   const float* __restrict__ b,
                                                   float* __restrict__ out,
                                                   int n, int leaky) {
    extern __shared__ __align__(16) __half sh[];
    __half (*sA)[PADK] = (__half(*)[PADK])sh;                // 128 rows
    __half (*sB)[PADK] = (__half(*)[PADK])(sh + 128 * PADK); // 64 rows
    __shared__ float sb[F];

    int t = threadIdx.x;
    int base = blockIdx.x * 128;

    // stage B: row r = out-feature, k<64 from Ws, k>=64 from Wn (float4 granules)
    for (int i = t; i < 64 * 32; i += 128) {
        int r = i >> 5, c4 = i & 31;
        int k0 = 4 * c4;
        float4 v = (k0 < 64) ? *(const float4*)(Ws + r * 64 + k0)
                             : *(const float4*)(Wn + r * 64 + (k0 - 64));
        *(__half2*)&sB[r][k0]     = __float22half2_rn(make_float2(v.x, v.y));
        *(__half2*)&sB[r][k0 + 2] = __float22half2_rn(make_float2(v.z, v.w));
    }
    // stage A: row r = local node, k<64 h, k>=64 agg (float4 granules)
    for (int i = t; i < 128 * 32; i += 128) {
        int r = i >> 5, c4 = i & 31;
        int k0 = 4 * c4;
        int node = base + r;
        float4 v = make_float4(0.f, 0.f, 0.f, 0.f);
        if (node < n) {
            v = (k0 < 64) ? *(const float4*)(h   + (size_t)node * F + k0)
                          : *(const float4*)(agg + (size_t)node * F + (k0 - 64));
        }
        *(__half2*)&sA[r][k0]     = __float22half2_rn(make_float2(v.x, v.y));
        *(__half2*)&sA[r][k0 + 2] = __float22half2_rn(make_float2(v.z, v.w));
    }
    if (t < F) sb[t] = b[t];
    __syncthreads();

    int lane = t & 31, w = t >> 5;
    int g  = lane >> 2;        // group id (0..7)
    int tg = lane & 3;         // thread-in-group (0..3)

    float acc[2][8][4];
    #pragma unroll
    for (int mt = 0; mt < 2; mt++)
        #pragma unroll
        for (int nt = 0; nt < 8; nt++)
            #pragma unroll
            for (int j = 0; j < 4; j++) acc[mt][nt][j] = 0.f;

    #pragma unroll
    for (int kt = 0; kt < 8; kt++) {
        int k0 = kt * 16 + tg * 2;
        uint32_t af[2][4];
        #pragma unroll
        for (int mt = 0; mt < 2; mt++) {
            int r0 = w * 32 + mt * 16 + g;
            af[mt][0] = *(const uint32_t*)&sA[r0][k0];
            af[mt][1] = *(const uint32_t*)&sA[r0 + 8][k0];
            af[mt][2] = *(const uint32_t*)&sA[r0][k0 + 8];
            af[mt][3] = *(const uint32_t*)&sA[r0 + 8][k0 + 8];
        }
        #pragma unroll
        for (int nt = 0; nt < 8; nt++) {
            uint32_t b0 = *(const uint32_t*)&sB[nt * 8 + g][k0];
            uint32_t b1 = *(const uint32_t*)&sB[nt * 8 + g][k0 + 8];
            mma16816(acc[0][nt], af[0], b0, b1);
            mma16816(acc[1][nt], af[1], b0, b1);
        }
    }

    // epilogue: d0,d1 -> (row g, cols 2tg,2tg+1); d2,d3 -> row g+8
    #pragma unroll
    for (int mt = 0; mt < 2; mt++) {
        int r0 = w * 32 + mt * 16 + g;
        int node0 = base + r0;
        int node1 = node0 + 8;
        #pragma unroll
        for (int nt = 0; nt < 8; nt++) {
            int col = nt * 8 + tg * 2;
            float bx = sb[col], by = sb[col + 1];
            float2 v0, v1;
            v0.x = acc[mt][nt][0] + bx;
            v0.y = acc[mt][nt][1] + by;
            v1.x = acc[mt][nt][2] + bx;
            v1.y = acc[mt][nt][3] + by;
            if (leaky) {
                v0.x = v0.x >= 0.f ? v0.x : 0.01f * v0.x;
                v0.y = v0.y >= 0.f ? v0.y : 0.01f * v0.y;
                v1.x = v1.x >= 0.f ? v1.x : 0.01f * v1.x;
                v1.y = v1.y >= 0.f ? v1.y : 0.01f * v1.y;
            }
            if (node0 < n) *(float2*)(out + (size_t)node0 * F + col) = v0;
            if (node1 < n) *(float2*)(out + (size_t)node1 * F + col) = v1;
        }
    }
}

// ---------------------------------------------------------------- launch

#define SMEM_TR ((128 + 64) * PADK * (int)sizeof(__half))   // 52224

extern "C" void kernel_launch(void* const* d_in, const int* in_sizes, int n_in,
                              void* d_out, int out_size) {
    const float* in_feat = (const float*)d_in[0];
    const int*   src     = (const int*)d_in[1];
    const int*   dst     = (const int*)d_in[2];
    const float* w_self1 = (const float*)d_in[3];
    const float* w_nei1  = (const float*)d_in[4];
    const float* b1      = (const float*)d_in[5];
    const float* w_self2 = (const float*)d_in[6];
    const float* w_nei2  = (const float*)d_in[7];
    const float* b2      = (const float*)d_in[8];
    const float* w_self3 = (const float*)d_in[9];
    const float* w_nei3  = (const float*)d_in[10];
    const float* b3      = (const float*)d_in[11];
    float* out = (float*)d_out;

    int n = in_sizes[0] / F;     // 100000
    int e = in_sizes[1];         // 1600000
    int nscan = (n + SCAN_BS - 1) / SCAN_BS;

    float *bufA, *bufB, *agg;
    int* counts;
    cudaGetSymbolAddress((void**)&bufA, g_bufA);
    cudaGetSymbolAddress((void**)&bufB, g_bufB);
    cudaGetSymbolAddress((void**)&agg,  g_agg);
    cudaGetSymbolAddress((void**)&counts, g_counts);

    cudaFuncSetAttribute(k_transform, cudaFuncAttributeMaxDynamicSharedMemorySize,
                         SMEM_TR);

    // ---- CSR build ----
    cudaMemsetAsync(counts, 0, (size_t)n * sizeof(int));       // launch 1
    k_hist<<<(e + 255) / 256, 256>>>(dst, e);                  // launch 2
    k_scan_lookback<<<nscan, SCAN_BS>>>(n);                    // launch 3
    k_scatter<<<(e + 255) / 256, 256>>>(src, dst, e);          // launch 4

    int agg_grid = (n * 32 + 255) / 256;   // warp per node
    int tr_grid  = (n + 127) / 128;        // 782

    // ---- layer 1 ----
    k_aggregate<<<agg_grid, 256>>>(in_feat, n);                // launch 5
    k_transform<<<tr_grid, 128, SMEM_TR>>>(in_feat, agg, w_self1, w_nei1,
                                           b1, bufA, n, 1);    // launch 6 (profiled)
    // ---- layer 2 ----
    k_aggregate<<<agg_grid, 256>>>(bufA, n);
    k_transform<<<tr_grid, 128, SMEM_TR>>>(bufA, agg, w_self2, w_nei2, b2, bufB, n, 1);
    // ---- layer 3 ----
    k_aggregate<<<agg_grid, 256>>>(bufB, n);
    k_transform<<<tr_grid, 128, SMEM_TR>>>(bufB, agg, w_self3, w_nei3, b3, out, n, 0);
}

// round 13
// speedup vs baseline: 1.8948x; 1.0161x over previous
#include <cuda_runtime.h>
#include <cuda_fp16.h>
#include <cstdint>

// GraphSAGE 3-layer, mean agg, N=100000, E=1600000, F=64.
// R13 (= R12 with the B-staging bug fixed: loop covered only k<64, leaving the
// Wn half of sB uninitialized -> NaN). All-fp16 feature pipeline:
// fp16 gathers (halve the LTS-capped aggregate), fp16 h/agg buffers,
// HMMA transform staging fp16 directly.

#define F 64
#define NMAX 100000
#define EMAX 1600000
#define SCAN_BS 512
#define PADK 136          // half-elements per smem row (272B = 17*16)

__device__ int g_counts[NMAX];
__device__ int g_cursor[NMAX];
__device__ int g_row_off[NMAX + 1];
__device__ unsigned long long g_scan_state[256];
__device__ int g_csr[EMAX];
__device__ __align__(16) __half g_h16[(size_t)NMAX * F];   // current layer input
__device__ __align__(16) __half g_a16[(size_t)NMAX * F];   // mean-neighbor agg

// ---------------------------------------------------------------- CSR build

__global__ void k_hist(const int* __restrict__ dst, int e) {
    if (blockIdx.x == 0 && threadIdx.x < 256) g_scan_state[threadIdx.x] = 0;
    int i = blockIdx.x * blockDim.x + threadIdx.x;
    if (i < e) atomicAdd(&g_counts[dst[i]], 1);
}

__global__ void k_scan_lookback(int n) {
    int bid = blockIdx.x;
    int t = threadIdx.x;
    int i = bid * SCAN_BS + t;
    int v = (i < n) ? g_counts[i] : 0;
    int lane = t & 31, wid = t >> 5;

    int incl = v;
    #pragma unroll
    for (int o = 1; o < 32; o <<= 1) {
        int x = __shfl_up_sync(0xffffffffu, incl, o);
        if (lane >= o) incl += x;
    }
    __shared__ int ws[16];
    if (lane == 31) ws[wid] = incl;
    __syncthreads();
    if (wid == 0) {
        int s = (lane < 16) ? ws[lane] : 0;
        #pragma unroll
        for (int o = 1; o < 16; o <<= 1) {
            int x = __shfl_up_sync(0xffffffffu, s, o);
            if (lane >= o) s += x;
        }
        if (lane < 16) ws[lane] = s;
    }
    __syncthreads();
    int excl_local = incl - v + (wid ? ws[wid - 1] : 0);
    int block_total = ws[15];

    __shared__ int s_exclpref;
    if (wid == 0) {
        if (bid == 0) {
            if (lane == 0) {
                atomicExch(&g_scan_state[0],
                           ((unsigned long long)2 << 32) | (unsigned)block_total);
                s_exclpref = 0;
            }
        } else {
            if (lane == 0)
                atomicExch(&g_scan_state[bid],
                           ((unsigned long long)1 << 32) | (unsigned)block_total);
            int excl = 0;
            int lb = bid - 1;
            while (true) {
                int idx = lb - lane;
                unsigned long long s = (idx >= 0)
                    ? *(volatile unsigned long long*)&g_scan_state[idx]
                    : ((unsigned long long)2 << 32);
                int st = (int)(s >> 32);
                if (__all_sync(0xffffffffu, st != 0)) {
                    unsigned pre = __ballot_sync(0xffffffffu, st == 2);
                    unsigned val = (unsigned)s;
                    if (pre) {
                        int fp = __ffs(pre) - 1;
                        int c = (lane <= fp) ? (int)val : 0;
                        #pragma unroll
                        for (int o = 16; o; o >>= 1)
                            c += __shfl_down_sync(0xffffffffu, c, o);
                        excl += __shfl_sync(0xffffffffu, c, 0);
                        break;
                    } else {
                        int c = (int)val;
                        #pragma unroll
                        for (int o = 16; o; o >>= 1)
                            c += __shfl_down_sync(0xffffffffu, c, o);
                        excl += __shfl_sync(0xffffffffu, c, 0);
                        lb -= 32;
                    }
                }
            }
            if (lane == 0) {
                atomicExch(&g_scan_state[bid],
                           ((unsigned long long)2 << 32) | (unsigned)(excl + block_total));
                s_exclpref = excl;
            }
        }
    }
    __syncthreads();
    int off = excl_local + s_exclpref;
    if (i < n) {
        g_row_off[i] = off;
        g_cursor[i]  = off;
        if (i == n - 1) g_row_off[n] = off + v;
    }
}

__global__ void k_scatter(const int* __restrict__ src, const int* __restrict__ dst, int e) {
    int i = blockIdx.x * blockDim.x + threadIdx.x;
    if (i < e) {
        int p = atomicAdd(&g_cursor[dst[i]], 1);
        g_csr[p] = src[i];
    }
}

// ---------------------------------------------------------------- fp16 convert

__global__ void k_tofp16(const float* __restrict__ in, int n2) {
    int i = blockIdx.x * blockDim.x + threadIdx.x;   // half2 slots
    if (i < n2) {
        float2 v = ((const float2*)in)[i];
        ((__half2*)g_h16)[i] = __float22half2_rn(v);
    }
}

// ---------------------------------------------------------------- aggregate

// One warp per node. Lane l owns features [2l, 2l+1]. Gather fp16 (1 line/row),
// accumulate fp32, write fp16 mean. 8-deep unroll.
__global__ void k_aggregate(int n) {
    int gtid = blockIdx.x * blockDim.x + threadIdx.x;
    int node = gtid >> 5;
    int lane = gtid & 31;
    if (node >= n) return;

    int beg = g_row_off[node];
    int end = g_row_off[node + 1];
    const __half2* hp = (const __half2*)g_h16;

    float ax = 0.f, ay = 0.f;
    int e = beg;
    for (; e + 8 <= end; e += 8) {
        int s0 = g_csr[e + 0], s1 = g_csr[e + 1], s2 = g_csr[e + 2], s3 = g_csr[e + 3];
        int s4 = g_csr[e + 4], s5 = g_csr[e + 5], s6 = g_csr[e + 6], s7 = g_csr[e + 7];
        float2 v0 = __half22float2(hp[(size_t)s0 * 32 + lane]);
        float2 v1 = __half22float2(hp[(size_t)s1 * 32 + lane]);
        float2 v2 = __half22float2(hp[(size_t)s2 * 32 + lane]);
        float2 v3 = __half22float2(hp[(size_t)s3 * 32 + lane]);
        float2 v4 = __half22float2(hp[(size_t)s4 * 32 + lane]);
        float2 v5 = __half22float2(hp[(size_t)s5 * 32 + lane]);
        float2 v6 = __half22float2(hp[(size_t)s6 * 32 + lane]);
        float2 v7 = __half22float2(hp[(size_t)s7 * 32 + lane]);
        ax += ((v0.x + v1.x) + (v2.x + v3.x)) + ((v4.x + v5.x) + (v6.x + v7.x));
        ay += ((v0.y + v1.y) + (v2.y + v3.y)) + ((v4.y + v5.y) + (v6.y + v7.y));
    }
    for (; e < end; e++) {
        float2 v = __half22float2(hp[(size_t)g_csr[e] * 32 + lane]);
        ax += v.x;
        ay += v.y;
    }
    int deg = end - beg;
    float inv = 1.f / (float)(deg > 0 ? deg : 1);
    ((__half2*)g_a16)[(size_t)node * 32 + lane] =
        __float22half2_rn(make_float2(ax * inv, ay * inv));
}

// ---------------------------------------------------------------- transform

__device__ __forceinline__ void mma16816(float* d, const uint32_t* a,
                                         uint32_t b0, uint32_t b1) {
    asm volatile(
        "mma.sync.aligned.m16n8k16.row.col.f32.f16.f16.f32 "
        "{%0,%1,%2,%3}, {%4,%5,%6,%7}, {%8,%9}, {%0,%1,%2,%3};"
        : "+f"(d[0]), "+f"(d[1]), "+f"(d[2]), "+f"(d[3])
        : "r"(a[0]), "r"(a[1]), "r"(a[2]), "r"(a[3]), "r"(b0), "r"(b1));
}

// Per block: 128 nodes. sA[128][PADK] = [h | agg] fp16 (staged from fp16 bufs),
// sB[64][PADK] = [Ws|Wn] fp16. Warp w computes rows [32w,32w+32) x 64 cols.
__global__ void __launch_bounds__(128) k_transform(const float* __restrict__ Ws,
                                                   const float* __restrict__ Wn,
                                                   const float* __restrict__ b,
                                                   float* __restrict__ out,
                                                   int n, int leaky, int write16) {
    extern __shared__ __align__(16) __half sh[];
    __half (*sA)[PADK] = (__half(*)[PADK])sh;                // 128 rows
    __half (*sB)[PADK] = (__half(*)[PADK])(sh + 128 * PADK); // 64 rows
    __shared__ float sb[F];

    int t = threadIdx.x;
    int base = blockIdx.x * 128;

    // stage B: fp32 weights -> fp16. 64 rows x 32 float4-granules (k0 = 0..124).
    for (int i = t; i < 64 * 32; i += 128) {
        int r = i >> 5, c4 = i & 31;          // FIXED (was >>4 / &15: Wn half unset)
        int k0 = 4 * c4;
        float4 v = (k0 < 64) ? *(const float4*)(Ws + r * 64 + k0)
                             : *(const float4*)(Wn + r * 64 + (k0 - 64));
        *(__half2*)&sB[r][k0]     = __float22half2_rn(make_float2(v.x, v.y));
        *(__half2*)&sB[r][k0 + 2] = __float22half2_rn(make_float2(v.z, v.w));
    }
    // stage A: direct fp16 copies, 8 halfs (uint4) per granule
    for (int i = t; i < 128 * 16; i += 128) {
        int r = i >> 4, c8 = i & 15;
        int k0 = 8 * c8;
        int node = base + r;
        uint4 v = make_uint4(0u, 0u, 0u, 0u);
        if (node < n) {
            v = (k0 < 64)
              ? *(const uint4*)(g_h16 + (size_t)node * F + k0)
              : *(const uint4*)(g_a16 + (size_t)node * F + (k0 - 64));
        }
        *(uint4*)&sA[r][k0] = v;
    }
    if (t < F) sb[t] = b[t];
    __syncthreads();

    int lane = t & 31, w = t >> 5;
    int g  = lane >> 2;        // group id (0..7)
    int tg = lane & 3;         // thread-in-group (0..3)

    float acc[2][8][4];
    #pragma unroll
    for (int mt = 0; mt < 2; mt++)
        #pragma unroll
        for (int nt = 0; nt < 8; nt++)
            #pragma unroll
            for (int j = 0; j < 4; j++) acc[mt][nt][j] = 0.f;

    #pragma unroll
    for (int kt = 0; kt < 8; kt++) {
        int k0 = kt * 16 + tg * 2;
        uint32_t af[2][4];
        #pragma unroll
        for (int mt = 0; mt < 2; mt++) {
            int r0 = w * 32 + mt * 16 + g;
            af[mt][0] = *(const uint32_t*)&sA[r0][k0];
            af[mt][1] = *(const uint32_t*)&sA[r0 + 8][k0];
            af[mt][2] = *(const uint32_t*)&sA[r0][k0 + 8];
            af[mt][3] = *(const uint32_t*)&sA[r0 + 8][k0 + 8];
        }
        #pragma unroll
        for (int nt = 0; nt < 8; nt++) {
            uint32_t b0 = *(const uint32_t*)&sB[nt * 8 + g][k0];
            uint32_t b1 = *(const uint32_t*)&sB[nt * 8 + g][k0 + 8];
            mma16816(acc[0][nt], af[0], b0, b1);
            mma16816(acc[1][nt], af[1], b0, b1);
        }
    }

    // epilogue: d0,d1 -> (row g, cols 2tg,2tg+1); d2,d3 -> row g+8
    #pragma unroll
    for (int mt = 0; mt < 2; mt++) {
        int r0 = w * 32 + mt * 16 + g;
        int node0 = base + r0;
        int node1 = node0 + 8;
        #pragma unroll
        for (int nt = 0; nt < 8; nt++) {
            int col = nt * 8 + tg * 2;
            float bx = sb[col], by = sb[col + 1];
            float2 v0, v1;
            v0.x = acc[mt][nt][0] + bx;
            v0.y = acc[mt][nt][1] + by;
            v1.x = acc[mt][nt][2] + bx;
            v1.y = acc[mt][nt][3] + by;
            if (leaky) {
                v0.x = v0.x >= 0.f ? v0.x : 0.01f * v0.x;
                v0.y = v0.y >= 0.f ? v0.y : 0.01f * v0.y;
                v1.x = v1.x >= 0.f ? v1.x : 0.01f * v1.x;
                v1.y = v1.y >= 0.f ? v1.y : 0.01f * v1.y;
            }
            if (node0 < n) {
                *(float2*)(out + (size_t)node0 * F + col) = v0;
                if (write16)
                    *(__half2*)(g_h16 + (size_t)node0 * F + col) = __float22half2_rn(v0);
            }
            if (node1 < n) {
                *(float2*)(out + (size_t)node1 * F + col) = v1;
                if (write16)
                    *(__half2*)(g_h16 + (size_t)node1 * F + col) = __float22half2_rn(v1);
            }
        }
    }
}

// ---------------------------------------------------------------- launch

#define SMEM_TR ((128 + 64) * PADK * (int)sizeof(__half))   // 52224

extern "C" void kernel_launch(void* const* d_in, const int* in_sizes, int n_in,
                              void* d_out, int out_size) {
    const float* in_feat = (const float*)d_in[0];
    const int*   src     = (const int*)d_in[1];
    const int*   dst     = (const int*)d_in[2];
    const float* w_self1 = (const float*)d_in[3];
    const float* w_nei1  = (const float*)d_in[4];
    const float* b1      = (const float*)d_in[5];
    const float* w_self2 = (const float*)d_in[6];
    const float* w_nei2  = (const float*)d_in[7];
    const float* b2      = (const float*)d_in[8];
    const float* w_self3 = (const float*)d_in[9];
    const float* w_nei3  = (const float*)d_in[10];
    const float* b3      = (const float*)d_in[11];
    float* out = (float*)d_out;

    int n = in_sizes[0] / F;     // 100000
    int e = in_sizes[1];         // 1600000
    int nscan = (n + SCAN_BS - 1) / SCAN_BS;

    int* counts;
    cudaGetSymbolAddress((void**)&counts, g_counts);

    cudaFuncSetAttribute(k_transform, cudaFuncAttributeMaxDynamicSharedMemorySize,
                         SMEM_TR);

    // ---- CSR build ----
    cudaMemsetAsync(counts, 0, (size_t)n * sizeof(int));
    k_hist<<<(e + 255) / 256, 256>>>(dst, e);                  // k1
    k_scan_lookback<<<nscan, SCAN_BS>>>(n);                    // k2
    k_scatter<<<(e + 255) / 256, 256>>>(src, dst, e);          // k3

    int n2 = n * F / 2;
    k_tofp16<<<(n2 + 255) / 256, 256>>>(in_feat, n2);          // k4

    int agg_grid = (n * 32 + 255) / 256;   // warp per node
    int tr_grid  = (n + 127) / 128;        // 782

    // layers 1-2 fp32 outputs are never read back (self term comes from g_h16),
    // so write them into d_out as scratch; layer 3 overwrites all of it.
    k_aggregate<<<agg_grid, 256>>>(n);                         // k5
    k_transform<<<tr_grid, 128, SMEM_TR>>>(w_self1, w_nei1, b1, out, n, 1, 1); // k6 (profiled)
    k_aggregate<<<agg_grid, 256>>>(n);
    k_transform<<<tr_grid, 128, SMEM_TR>>>(w_self2, w_nei2, b2, out, n, 1, 1);
    k_aggregate<<<agg_grid, 256>>>(n);
    k_transform<<<tr_grid, 128, SMEM_TR>>>(w_self3, w_nei3, b3, out, n, 0, 0);
}

// round 14
// speedup vs baseline: 2.1787x; 1.1498x over previous
#include <cuda_runtime.h>
#include <cuda_fp16.h>
#include <cstdint>

// GraphSAGE 3-layer, mean agg, N=100000, E=1600000, F=64.
// R14: transform widened to 256 threads (was 128: latency-bound staging at
//      ~14 warps/SM); fp16 convert folded into k_hist (saves a 12us serial
//      kernel). Aggregate + CSR unchanged from R13.

#define F 64
#define NMAX 100000
#define EMAX 1600000
#define SCAN_BS 512
#define PADK 136          // half-elements per smem row (272B = 17*16)

__device__ int g_counts[NMAX];
__device__ int g_cursor[NMAX];
__device__ int g_row_off[NMAX + 1];
__device__ unsigned long long g_scan_state[256];
__device__ int g_csr[EMAX];
__device__ __align__(16) __half g_h16[(size_t)NMAX * F];   // current layer input
__device__ __align__(16) __half g_a16[(size_t)NMAX * F];   // mean-neighbor agg

// ------------------------------------------- CSR build (+ fused fp16 convert)

// One kernel: zero scan state, convert in_feat -> fp16, histogram dst.
// Grid covers max(n2, e) elements.
__global__ void k_hist_cvt(const int* __restrict__ dst, int e,
                           const float* __restrict__ in, int n2) {
    int i = blockIdx.x * blockDim.x + threadIdx.x;
    if (i < 256) g_scan_state[i] = 0;
    if (i < n2) {
        float2 v = ((const float2*)in)[i];
        ((__half2*)g_h16)[i] = __float22half2_rn(v);
    }
    if (i < e) atomicAdd(&g_counts[dst[i]], 1);
}

__global__ void k_scan_lookback(int n) {
    int bid = blockIdx.x;
    int t = threadIdx.x;
    int i = bid * SCAN_BS + t;
    int v = (i < n) ? g_counts[i] : 0;
    int lane = t & 31, wid = t >> 5;

    int incl = v;
    #pragma unroll
    for (int o = 1; o < 32; o <<= 1) {
        int x = __shfl_up_sync(0xffffffffu, incl, o);
        if (lane >= o) incl += x;
    }
    __shared__ int ws[16];
    if (lane == 31) ws[wid] = incl;
    __syncthreads();
    if (wid == 0) {
        int s = (lane < 16) ? ws[lane] : 0;
        #pragma unroll
        for (int o = 1; o < 16; o <<= 1) {
            int x = __shfl_up_sync(0xffffffffu, s, o);
            if (lane >= o) s += x;
        }
        if (lane < 16) ws[lane] = s;
    }
    __syncthreads();
    int excl_local = incl - v + (wid ? ws[wid - 1] : 0);
    int block_total = ws[15];

    __shared__ int s_exclpref;
    if (wid == 0) {
        if (bid == 0) {
            if (lane == 0) {
                atomicExch(&g_scan_state[0],
                           ((unsigned long long)2 << 32) | (unsigned)block_total);
                s_exclpref = 0;
            }
        } else {
            if (lane == 0)
                atomicExch(&g_scan_state[bid],
                           ((unsigned long long)1 << 32) | (unsigned)block_total);
            int excl = 0;
            int lb = bid - 1;
            while (true) {
                int idx = lb - lane;
                unsigned long long s = (idx >= 0)
                    ? *(volatile unsigned long long*)&g_scan_state[idx]
                    : ((unsigned long long)2 << 32);
                int st = (int)(s >> 32);
                if (__all_sync(0xffffffffu, st != 0)) {
                    unsigned pre = __ballot_sync(0xffffffffu, st == 2);
                    unsigned val = (unsigned)s;
                    if (pre) {
                        int fp = __ffs(pre) - 1;
                        int c = (lane <= fp) ? (int)val : 0;
                        #pragma unroll
                        for (int o = 16; o; o >>= 1)
                            c += __shfl_down_sync(0xffffffffu, c, o);
                        excl += __shfl_sync(0xffffffffu, c, 0);
                        break;
                    } else {
                        int c = (int)val;
                        #pragma unroll
                        for (int o = 16; o; o >>= 1)
                            c += __shfl_down_sync(0xffffffffu, c, o);
                        excl += __shfl_sync(0xffffffffu, c, 0);
                        lb -= 32;
                    }
                }
            }
            if (lane == 0) {
                atomicExch(&g_scan_state[bid],
                           ((unsigned long long)2 << 32) | (unsigned)(excl + block_total));
                s_exclpref = excl;
            }
        }
    }
    __syncthreads();
    int off = excl_local + s_exclpref;
    if (i < n) {
        g_row_off[i] = off;
        g_cursor[i]  = off;
        if (i == n - 1) g_row_off[n] = off + v;
    }
}

__global__ void k_scatter(const int* __restrict__ src, const int* __restrict__ dst, int e) {
    int i = blockIdx.x * blockDim.x + threadIdx.x;
    if (i < e) {
        int p = atomicAdd(&g_cursor[dst[i]], 1);
        g_csr[p] = src[i];
    }
}

// ---------------------------------------------------------------- aggregate

// One warp per node. Lane l owns features [2l, 2l+1]. Gather fp16, accum fp32,
// write fp16 mean. 8-deep unroll.
__global__ void k_aggregate(int n) {
    int gtid = blockIdx.x * blockDim.x + threadIdx.x;
    int node = gtid >> 5;
    int lane = gtid & 31;
    if (node >= n) return;

    int beg = g_row_off[node];
    int end = g_row_off[node + 1];
    const __half2* hp = (const __half2*)g_h16;

    float ax = 0.f, ay = 0.f;
    int e = beg;
    for (; e + 8 <= end; e += 8) {
        int s0 = g_csr[e + 0], s1 = g_csr[e + 1], s2 = g_csr[e + 2], s3 = g_csr[e + 3];
        int s4 = g_csr[e + 4], s5 = g_csr[e + 5], s6 = g_csr[e + 6], s7 = g_csr[e + 7];
        float2 v0 = __half22float2(hp[(size_t)s0 * 32 + lane]);
        float2 v1 = __half22float2(hp[(size_t)s1 * 32 + lane]);
        float2 v2 = __half22float2(hp[(size_t)s2 * 32 + lane]);
        float2 v3 = __half22float2(hp[(size_t)s3 * 32 + lane]);
        float2 v4 = __half22float2(hp[(size_t)s4 * 32 + lane]);
        float2 v5 = __half22float2(hp[(size_t)s5 * 32 + lane]);
        float2 v6 = __half22float2(hp[(size_t)s6 * 32 + lane]);
        float2 v7 = __half22float2(hp[(size_t)s7 * 32 + lane]);
        ax += ((v0.x + v1.x) + (v2.x + v3.x)) + ((v4.x + v5.x) + (v6.x + v7.x));
        ay += ((v0.y + v1.y) + (v2.y + v3.y)) + ((v4.y + v5.y) + (v6.y + v7.y));
    }
    for (; e < end; e++) {
        float2 v = __half22float2(hp[(size_t)g_csr[e] * 32 + lane]);
        ax += v.x;
        ay += v.y;
    }
    int deg = end - beg;
    float inv = 1.f / (float)(deg > 0 ? deg : 1);
    ((__half2*)g_a16)[(size_t)node * 32 + lane] =
        __float22half2_rn(make_float2(ax * inv, ay * inv));
}

// ---------------------------------------------------------------- transform

__device__ __forceinline__ void mma16816(float* d, const uint32_t* a,
                                         uint32_t b0, uint32_t b1) {
    asm volatile(
        "mma.sync.aligned.m16n8k16.row.col.f32.f16.f16.f32 "
        "{%0,%1,%2,%3}, {%4,%5,%6,%7}, {%8,%9}, {%0,%1,%2,%3};"
        : "+f"(d[0]), "+f"(d[1]), "+f"(d[2]), "+f"(d[3])
        : "r"(a[0]), "r"(a[1]), "r"(a[2]), "r"(a[3]), "r"(b0), "r"(b1));
}

// 256 threads per 128-node tile. sA[128][PADK] = [h|agg] fp16, sB[64][PADK] =
// [Ws|Wn] fp16. Warp w (0..7) computes the 16-row stripe [16w, 16w+16) x 64.
__global__ void __launch_bounds__(256) k_transform(const float* __restrict__ Ws,
                                                   const float* __restrict__ Wn,
                                                   const float* __restrict__ b,
                                                   float* __restrict__ out,
                                                   int n, int leaky, int write16) {
    extern __shared__ __align__(16) __half sh[];
    __half (*sA)[PADK] = (__half(*)[PADK])sh;                // 128 rows
    __half (*sB)[PADK] = (__half(*)[PADK])(sh + 128 * PADK); // 64 rows
    __shared__ float sb[F];

    int t = threadIdx.x;
    int base = blockIdx.x * 128;

    // stage B: fp32 weights -> fp16. 64 rows x 32 float4-granules (k0 = 0..124).
    for (int i = t; i < 64 * 32; i += 256) {
        int r = i >> 5, c4 = i & 31;
        int k0 = 4 * c4;
        float4 v = (k0 < 64) ? *(const float4*)(Ws + r * 64 + k0)
                             : *(const float4*)(Wn + r * 64 + (k0 - 64));
        *(__half2*)&sB[r][k0]     = __float22half2_rn(make_float2(v.x, v.y));
        *(__half2*)&sB[r][k0 + 2] = __float22half2_rn(make_float2(v.z, v.w));
    }
    // stage A: direct fp16 copies, 8 halfs (uint4) per granule
    for (int i = t; i < 128 * 16; i += 256) {
        int r = i >> 4, c8 = i & 15;
        int k0 = 8 * c8;
        int node = base + r;
        uint4 v = make_uint4(0u, 0u, 0u, 0u);
        if (node < n) {
            v = (k0 < 64)
              ? *(const uint4*)(g_h16 + (size_t)node * F + k0)
              : *(const uint4*)(g_a16 + (size_t)node * F + (k0 - 64));
        }
        *(uint4*)&sA[r][k0] = v;
    }
    if (t < F) sb[t] = b[t];
    __syncthreads();

    int lane = t & 31, w = t >> 5;       // w = 0..7
    int g  = lane >> 2;                  // group id (0..7)
    int tg = lane & 3;                   // thread-in-group (0..3)

    float acc[8][4];
    #pragma unroll
    for (int nt = 0; nt < 8; nt++)
        #pragma unroll
        for (int j = 0; j < 4; j++) acc[nt][j] = 0.f;

    int r0 = w * 16 + g;
    #pragma unroll
    for (int kt = 0; kt < 8; kt++) {
        int k0 = kt * 16 + tg * 2;
        uint32_t af[4];
        af[0] = *(const uint32_t*)&sA[r0][k0];
        af[1] = *(const uint32_t*)&sA[r0 + 8][k0];
        af[2] = *(const uint32_t*)&sA[r0][k0 + 8];
        af[3] = *(const uint32_t*)&sA[r0 + 8][k0 + 8];
        #pragma unroll
        for (int nt = 0; nt < 8; nt++) {
            uint32_t b0 = *(const uint32_t*)&sB[nt * 8 + g][k0];
            uint32_t b1 = *(const uint32_t*)&sB[nt * 8 + g][k0 + 8];
            mma16816(acc[nt], af, b0, b1);
        }
    }

    // epilogue: d0,d1 -> (row r0, cols 2tg,2tg+1); d2,d3 -> row r0+8
    int node0 = base + r0;
    int node1 = node0 + 8;
    #pragma unroll
    for (int nt = 0; nt < 8; nt++) {
        int col = nt * 8 + tg * 2;
        float bx = sb[col], by = sb[col + 1];
        float2 v0, v1;
        v0.x = acc[nt][0] + bx;
        v0.y = acc[nt][1] + by;
        v1.x = acc[nt][2] + bx;
        v1.y = acc[nt][3] + by;
        if (leaky) {
            v0.x = v0.x >= 0.f ? v0.x : 0.01f * v0.x;
            v0.y = v0.y >= 0.f ? v0.y : 0.01f * v0.y;
            v1.x = v1.x >= 0.f ? v1.x : 0.01f * v1.x;
            v1.y = v1.y >= 0.f ? v1.y : 0.01f * v1.y;
        }
        if (node0 < n) {
            *(float2*)(out + (size_t)node0 * F + col) = v0;
            if (write16)
                *(__half2*)(g_h16 + (size_t)node0 * F + col) = __float22half2_rn(v0);
        }
        if (node1 < n) {
            *(float2*)(out + (size_t)node1 * F + col) = v1;
            if (write16)
                *(__half2*)(g_h16 + (size_t)node1 * F + col) = __float22half2_rn(v1);
        }
    }
}

// ---------------------------------------------------------------- launch

#define SMEM_TR ((128 + 64) * PADK * (int)sizeof(__half))   // 52224

extern "C" void kernel_launch(void* const* d_in, const int* in_sizes, int n_in,
                              void* d_out, int out_size) {
    const float* in_feat = (const float*)d_in[0];
    const int*   src     = (const int*)d_in[1];
    const int*   dst     = (const int*)d_in[2];
    const float* w_self1 = (const float*)d_in[3];
    const float* w_nei1  = (const float*)d_in[4];
    const float* b1      = (const float*)d_in[5];
    const float* w_self2 = (const float*)d_in[6];
    const float* w_nei2  = (const float*)d_in[7];
    const float* b2      = (const float*)d_in[8];
    const float* w_self3 = (const float*)d_in[9];
    const float* w_nei3  = (const float*)d_in[10];
    const float* b3      = (const float*)d_in[11];
    float* out = (float*)d_out;

    int n = in_sizes[0] / F;     // 100000
    int e = in_sizes[1];         // 1600000
    int nscan = (n + SCAN_BS - 1) / SCAN_BS;
    int n2 = n * F / 2;          // 3.2M half2 slots

    int* counts;
    cudaGetSymbolAddress((void**)&counts, g_counts);

    cudaFuncSetAttribute(k_transform, cudaFuncAttributeMaxDynamicSharedMemorySize,
                         SMEM_TR);

    // ---- CSR build + fp16 convert (fused) ----
    cudaMemsetAsync(counts, 0, (size_t)n * sizeof(int));
    int hc_items = (n2 > e) ? n2 : e;
    k_hist_cvt<<<(hc_items + 255) / 256, 256>>>(dst, e, in_feat, n2);
    k_scan_lookback<<<nscan, SCAN_BS>>>(n);
    k_scatter<<<(e + 255) / 256, 256>>>(src, dst, e);

    int agg_grid = (n * 32 + 255) / 256;   // warp per node
    int tr_grid  = (n + 127) / 128;        // 782

    // layers 1-2 fp32 outputs are never read back (self term comes from g_h16),
    // so write them into d_out as scratch; layer 3 overwrites all of it.
    k_aggregate<<<agg_grid, 256>>>(n);
    k_transform<<<tr_grid, 256, SMEM_TR>>>(w_self1, w_nei1, b1, out, n, 1, 1);
    k_aggregate<<<agg_grid, 256>>>(n);
    k_transform<<<tr_grid, 256, SMEM_TR>>>(w_self2, w_nei2, b2, out, n, 1, 1);
    k_aggregate<<<agg_grid, 256>>>(n);
    k_transform<<<tr_grid, 256, SMEM_TR>>>(w_self3, w_nei3, b3, out, n, 0, 0);
}

// round 15
// speedup vs baseline: 2.5340x; 1.1630x over previous
#include <cuda_runtime.h>
#include <cuda_fp16.h>
#include <cstdint>

// GraphSAGE 3-layer, mean agg, N=100000, E=1600000, F=64.
// R15: aggregate is ISSUE-bound (67% issue, 42% alu, L2 only 23%) -> cut
//      instructions/edge ~2x: 2 nodes/warp with LDG.64 gathers (lane owns 4
//      features), byte-offset CSR (no IMAD.WIDE), depth-1 HADD2 edge pairing
//      (halves cvt+add). Transform/CSR otherwise unchanged from R14.

#define F 64
#define NMAX 100000
#define EMAX 1600000
#define SCAN_BS 512
#define PADK 136          // half-elements per smem row (272B = 17*16)

__device__ int g_counts[NMAX];
__device__ int g_cursor[NMAX];
__device__ int g_row_off[NMAX + 1];
__device__ unsigned long long g_scan_state[256];
__device__ int g_csr[EMAX];                                // BYTE offsets (src*128)
__device__ __align__(16) __half g_h16[(size_t)NMAX * F];   // current layer input
__device__ __align__(16) __half g_a16[(size_t)NMAX * F];   // mean-neighbor agg

// ------------------------------------------- CSR build (+ fused fp16 convert)

__global__ void k_hist_cvt(const int* __restrict__ dst, int e,
                           const float* __restrict__ in, int n2) {
    int i = blockIdx.x * blockDim.x + threadIdx.x;
    if (i < 256) g_scan_state[i] = 0;
    if (i < n2) {
        float2 v = ((const float2*)in)[i];
        ((__half2*)g_h16)[i] = __float22half2_rn(v);
    }
    if (i < e) atomicAdd(&g_counts[dst[i]], 1);
}

__global__ void k_scan_lookback(int n) {
    int bid = blockIdx.x;
    int t = threadIdx.x;
    int i = bid * SCAN_BS + t;
    int v = (i < n) ? g_counts[i] : 0;
    int lane = t & 31, wid = t >> 5;

    int incl = v;
    #pragma unroll
    for (int o = 1; o < 32; o <<= 1) {
        int x = __shfl_up_sync(0xffffffffu, incl, o);
        if (lane >= o) incl += x;
    }
    __shared__ int ws[16];
    if (lane == 31) ws[wid] = incl;
    __syncthreads();
    if (wid == 0) {
        int s = (lane < 16) ? ws[lane] : 0;
        #pragma unroll
        for (int o = 1; o < 16; o <<= 1) {
            int x = __shfl_up_sync(0xffffffffu, s, o);
            if (lane >= o) s += x;
        }
        if (lane < 16) ws[lane] = s;
    }
    __syncthreads();
    int excl_local = incl - v + (wid ? ws[wid - 1] : 0);
    int block_total = ws[15];

    __shared__ int s_exclpref;
    if (wid == 0) {
        if (bid == 0) {
            if (lane == 0) {
                atomicExch(&g_scan_state[0],
                           ((unsigned long long)2 << 32) | (unsigned)block_total);
                s_exclpref = 0;
            }
        } else {
            if (lane == 0)
                atomicExch(&g_scan_state[bid],
                           ((unsigned long long)1 << 32) | (unsigned)block_total);
            int excl = 0;
            int lb = bid - 1;
            while (true) {
                int idx = lb - lane;
                unsigned long long s = (idx >= 0)
                    ? *(volatile unsigned long long*)&g_scan_state[idx]
                    : ((unsigned long long)2 << 32);
                int st = (int)(s >> 32);
                if (__all_sync(0xffffffffu, st != 0)) {
                    unsigned pre = __ballot_sync(0xffffffffu, st == 2);
                    unsigned val = (unsigned)s;
                    if (pre) {
                        int fp = __ffs(pre) - 1;
                        int c = (lane <= fp) ? (int)val : 0;
                        #pragma unroll
                        for (int o = 16; o; o >>= 1)
                            c += __shfl_down_sync(0xffffffffu, c, o);
                        excl += __shfl_sync(0xffffffffu, c, 0);
                        break;
                    } else {
                        int c = (int)val;
                        #pragma unroll
                        for (int o = 16; o; o >>= 1)
                            c += __shfl_down_sync(0xffffffffu, c, o);
                        excl += __shfl_sync(0xffffffffu, c, 0);
                        lb -= 32;
                    }
                }
            }
            if (lane == 0) {
                atomicExch(&g_scan_state[bid],
                           ((unsigned long long)2 << 32) | (unsigned)(excl + block_total));
                s_exclpref = excl;
            }
        }
    }
    __syncthreads();
    int off = excl_local + s_exclpref;
    if (i < n) {
        g_row_off[i] = off;
        g_cursor[i]  = off;
        if (i == n - 1) g_row_off[n] = off + v;
    }
}

// Stores BYTE offsets (src * 128 = src row start in g_h16).
__global__ void k_scatter(const int* __restrict__ src, const int* __restrict__ dst, int e) {
    int i = blockIdx.x * blockDim.x + threadIdx.x;
    if (i < e) {
        int p = atomicAdd(&g_cursor[dst[i]], 1);
        g_csr[p] = src[i] << 7;          // *128 bytes
    }
}

// ---------------------------------------------------------------- aggregate

__device__ __forceinline__ __half2 u2h(unsigned u) {
    return *reinterpret_cast<__half2*>(&u);
}
__device__ __forceinline__ unsigned h2u(__half2 h) {
    return *reinterpret_cast<unsigned*>(&h);
}

// 2 nodes per warp; lane16 owns features [4*l16, 4*l16+3] (uint2 = 2 half2).
// 8-edge windows: pair adjacent edges with HADD2, then fp32 accumulate.
__global__ void k_aggregate(int n) {
    int gtid = blockIdx.x * blockDim.x + threadIdx.x;
    int warp = gtid >> 5;
    int lane = gtid & 31;
    int hw   = lane >> 4;        // half-warp: which of the 2 nodes
    int l16  = lane & 15;
    int node = warp * 2 + hw;
    if (node >= n) return;

    int beg = g_row_off[node];
    int end = g_row_off[node + 1];
    const char* hbase = (const char*)g_h16 + l16 * 8;

    float f0 = 0.f, f1 = 0.f, f2 = 0.f, f3 = 0.f;
    int e = beg;
    for (; e + 8 <= end; e += 8) {
        int o0 = g_csr[e + 0], o1 = g_csr[e + 1], o2 = g_csr[e + 2], o3 = g_csr[e + 3];
        int o4 = g_csr[e + 4], o5 = g_csr[e + 5], o6 = g_csr[e + 6], o7 = g_csr[e + 7];
        uint2 v0 = *(const uint2*)(hbase + o0);
        uint2 v1 = *(const uint2*)(hbase + o1);
        uint2 v2 = *(const uint2*)(hbase + o2);
        uint2 v3 = *(const uint2*)(hbase + o3);
        uint2 v4 = *(const uint2*)(hbase + o4);
        uint2 v5 = *(const uint2*)(hbase + o5);
        uint2 v6 = *(const uint2*)(hbase + o6);
        uint2 v7 = *(const uint2*)(hbase + o7);
        // depth-1 fp16 pairing (edges 0+1, 2+3, 4+5, 6+7)
        __half2 p0x = __hadd2(u2h(v0.x), u2h(v1.x)), p0y = __hadd2(u2h(v0.y), u2h(v1.y));
        __half2 p1x = __hadd2(u2h(v2.x), u2h(v3.x)), p1y = __hadd2(u2h(v2.y), u2h(v3.y));
        __half2 p2x = __hadd2(u2h(v4.x), u2h(v5.x)), p2y = __hadd2(u2h(v4.y), u2h(v5.y));
        __half2 p3x = __hadd2(u2h(v6.x), u2h(v7.x)), p3y = __hadd2(u2h(v6.y), u2h(v7.y));
        float2 a0 = __half22float2(p0x), b0 = __half22float2(p0y);
        float2 a1 = __half22float2(p1x), b1 = __half22float2(p1y);
        float2 a2 = __half22float2(p2x), b2 = __half22float2(p2y);
        float2 a3 = __half22float2(p3x), b3 = __half22float2(p3y);
        f0 += (a0.x + a1.x) + (a2.x + a3.x);
        f1 += (a0.y + a1.y) + (a2.y + a3.y);
        f2 += (b0.x + b1.x) + (b2.x + b3.x);
        f3 += (b0.y + b1.y) + (b2.y + b3.y);
    }
    for (; e < end; e++) {
        uint2 v = *(const uint2*)(hbase + g_csr[e]);
        float2 a = __half22float2(u2h(v.x));
        float2 b = __half22float2(u2h(v.y));
        f0 += a.x; f1 += a.y; f2 += b.x; f3 += b.y;
    }

    int deg = end - beg;
    float inv = 1.f / (float)(deg > 0 ? deg : 1);
    uint2 w;
    w.x = h2u(__float22half2_rn(make_float2(f0 * inv, f1 * inv)));
    w.y = h2u(__float22half2_rn(make_float2(f2 * inv, f3 * inv)));
    *(uint2*)((char*)g_a16 + (size_t)node * 128 + l16 * 8) = w;
}

// ---------------------------------------------------------------- transform

__device__ __forceinline__ void mma16816(float* d, const uint32_t* a,
                                         uint32_t b0, uint32_t b1) {
    asm volatile(
        "mma.sync.aligned.m16n8k16.row.col.f32.f16.f16.f32 "
        "{%0,%1,%2,%3}, {%4,%5,%6,%7}, {%8,%9}, {%0,%1,%2,%3};"
        : "+f"(d[0]), "+f"(d[1]), "+f"(d[2]), "+f"(d[3])
        : "r"(a[0]), "r"(a[1]), "r"(a[2]), "r"(a[3]), "r"(b0), "r"(b1));
}

// 256 threads per 128-node tile. Warp w (0..7) computes stripe [16w,16w+16).
__global__ void __launch_bounds__(256) k_transform(const float* __restrict__ Ws,
                                                   const float* __restrict__ Wn,
                                                   const float* __restrict__ b,
                                                   float* __restrict__ out,
                                                   int n, int leaky, int write16) {
    extern __shared__ __align__(16) __half sh[];
    __half (*sA)[PADK] = (__half(*)[PADK])sh;                // 128 rows
    __half (*sB)[PADK] = (__half(*)[PADK])(sh + 128 * PADK); // 64 rows
    __shared__ float sb[F];

    int t = threadIdx.x;
    int base = blockIdx.x * 128;

    for (int i = t; i < 64 * 32; i += 256) {
        int r = i >> 5, c4 = i & 31;
        int k0 = 4 * c4;
        float4 v = (k0 < 64) ? *(const float4*)(Ws + r * 64 + k0)
                             : *(const float4*)(Wn + r * 64 + (k0 - 64));
        *(__half2*)&sB[r][k0]     = __float22half2_rn(make_float2(v.x, v.y));
        *(__half2*)&sB[r][k0 + 2] = __float22half2_rn(make_float2(v.z, v.w));
    }
    for (int i = t; i < 128 * 16; i += 256) {
        int r = i >> 4, c8 = i & 15;
        int k0 = 8 * c8;
        int node = base + r;
        uint4 v = make_uint4(0u, 0u, 0u, 0u);
        if (node < n) {
            v = (k0 < 64)
              ? *(const uint4*)(g_h16 + (size_t)node * F + k0)
              : *(const uint4*)(g_a16 + (size_t)node * F + (k0 - 64));
        }
        *(uint4*)&sA[r][k0] = v;
    }
    if (t < F) sb[t] = b[t];
    __syncthreads();

    int lane = t & 31, w = t >> 5;
    int g  = lane >> 2;
    int tg = lane & 3;

    float acc[8][4];
    #pragma unroll
    for (int nt = 0; nt < 8; nt++)
        #pragma unroll
        for (int j = 0; j < 4; j++) acc[nt][j] = 0.f;

    int r0 = w * 16 + g;
    #pragma unroll
    for (int kt = 0; kt < 8; kt++) {
        int k0 = kt * 16 + tg * 2;
        uint32_t af[4];
        af[0] = *(const uint32_t*)&sA[r0][k0];
        af[1] = *(const uint32_t*)&sA[r0 + 8][k0];
        af[2] = *(const uint32_t*)&sA[r0][k0 + 8];
        af[3] = *(const uint32_t*)&sA[r0 + 8][k0 + 8];
        #pragma unroll
        for (int nt = 0; nt < 8; nt++) {
            uint32_t b0 = *(const uint32_t*)&sB[nt * 8 + g][k0];
            uint32_t b1 = *(const uint32_t*)&sB[nt * 8 + g][k0 + 8];
            mma16816(acc[nt], af, b0, b1);
        }
    }

    int node0 = base + r0;
    int node1 = node0 + 8;
    #pragma unroll
    for (int nt = 0; nt < 8; nt++) {
        int col = nt * 8 + tg * 2;
        float bx = sb[col], by = sb[col + 1];
        float2 v0, v1;
        v0.x = acc[nt][0] + bx;
        v0.y = acc[nt][1] + by;
        v1.x = acc[nt][2] + bx;
        v1.y = acc[nt][3] + by;
        if (leaky) {
            v0.x = v0.x >= 0.f ? v0.x : 0.01f * v0.x;
            v0.y = v0.y >= 0.f ? v0.y : 0.01f * v0.y;
            v1.x = v1.x >= 0.f ? v1.x : 0.01f * v1.x;
            v1.y = v1.y >= 0.f ? v1.y : 0.01f * v1.y;
        }
        if (node0 < n) {
            *(float2*)(out + (size_t)node0 * F + col) = v0;
            if (write16)
                *(__half2*)(g_h16 + (size_t)node0 * F + col) = __float22half2_rn(v0);
        }
        if (node1 < n) {
            *(float2*)(out + (size_t)node1 * F + col) = v1;
            if (write16)
                *(__half2*)(g_h16 + (size_t)node1 * F + col) = __float22half2_rn(v1);
        }
    }
}

// ---------------------------------------------------------------- launch

#define SMEM_TR ((128 + 64) * PADK * (int)sizeof(__half))   // 52224

extern "C" void kernel_launch(void* const* d_in, const int* in_sizes, int n_in,
                              void* d_out, int out_size) {
    const float* in_feat = (const float*)d_in[0];
    const int*   src     = (const int*)d_in[1];
    const int*   dst     = (const int*)d_in[2];
    const float* w_self1 = (const float*)d_in[3];
    const float* w_nei1  = (const float*)d_in[4];
    const float* b1      = (const float*)d_in[5];
    const float* w_self2 = (const float*)d_in[6];
    const float* w_nei2  = (const float*)d_in[7];
    const float* b2      = (const float*)d_in[8];
    const float* w_self3 = (const float*)d_in[9];
    const float* w_nei3  = (const float*)d_in[10];
    const float* b3      = (const float*)d_in[11];
    float* out = (float*)d_out;

    int n = in_sizes[0] / F;     // 100000
    int e = in_sizes[1];         // 1600000
    int nscan = (n + SCAN_BS - 1) / SCAN_BS;
    int n2 = n * F / 2;

    int* counts;
    cudaGetSymbolAddress((void**)&counts, g_counts);

    cudaFuncSetAttribute(k_transform, cudaFuncAttributeMaxDynamicSharedMemorySize,
                         SMEM_TR);

    // ---- CSR build + fp16 convert (fused) ----
    cudaMemsetAsync(counts, 0, (size_t)n * sizeof(int));
    int hc_items = (n2 > e) ? n2 : e;
    k_hist_cvt<<<(hc_items + 255) / 256, 256>>>(dst, e, in_feat, n2);
    k_scan_lookback<<<nscan, SCAN_BS>>>(n);
    k_scatter<<<(e + 255) / 256, 256>>>(src, dst, e);

    int agg_grid = ((n + 1) / 2 * 32 + 255) / 256;   // 2 nodes per warp
    int tr_grid  = (n + 127) / 128;

    k_aggregate<<<agg_grid, 256>>>(n);
    k_transform<<<tr_grid, 256, SMEM_TR>>>(w_self1, w_nei1, b1, out, n, 1, 1);
    k_aggregate<<<agg_grid, 256>>>(n);
    k_transform<<<tr_grid, 256, SMEM_TR>>>(w_self2, w_nei2, b2, out, n, 1, 1);
    k_aggregate<<<agg_grid, 256>>>(n);
    k_transform<<<tr_grid, 256, SMEM_TR>>>(w_self3, w_nei3, b3, out, n, 0, 0);
}

// round 16
// speedup vs baseline: 2.8093x; 1.1086x over previous
#include <cuda_runtime.h>
#include <cuda_fp16.h>
#include <cstdint>

// GraphSAGE 3-layer, mean agg, N=100000, E=1600000, F=64.
// R16: aggregate instruction count cut again: 4 nodes/warp (8 lanes/node,
//      LDG.128 row gathers) + depth-2 fp16 pairwise adds -> 2.25 instr/edge
//      (was 3.4). Dead fp32 out-stores for layers 1-2 eliminated.
//      CSR + HMMA transform otherwise unchanged from R15 (188us).

#define F 64
#define NMAX 100000
#define EMAX 1600000
#define SCAN_BS 512
#define PADK 136          // half-elements per smem row (272B = 17*16)

__device__ int g_counts[NMAX];
__device__ int g_cursor[NMAX];
__device__ int g_row_off[NMAX + 1];
__device__ unsigned long long g_scan_state[256];
__device__ int g_csr[EMAX];                                // BYTE offsets (src*128)
__device__ __align__(16) __half g_h16[(size_t)NMAX * F];   // current layer input
__device__ __align__(16) __half g_a16[(size_t)NMAX * F];   // mean-neighbor agg

// ------------------------------------------- CSR build (+ fused fp16 convert)

__global__ void k_hist_cvt(const int* __restrict__ dst, int e,
                           const float* __restrict__ in, int n2) {
    int i = blockIdx.x * blockDim.x + threadIdx.x;
    if (i < 256) g_scan_state[i] = 0;
    if (i < n2) {
        float2 v = ((const float2*)in)[i];
        ((__half2*)g_h16)[i] = __float22half2_rn(v);
    }
    if (i < e) atomicAdd(&g_counts[dst[i]], 1);
}

__global__ void k_scan_lookback(int n) {
    int bid = blockIdx.x;
    int t = threadIdx.x;
    int i = bid * SCAN_BS + t;
    int v = (i < n) ? g_counts[i] : 0;
    int lane = t & 31, wid = t >> 5;

    int incl = v;
    #pragma unroll
    for (int o = 1; o < 32; o <<= 1) {
        int x = __shfl_up_sync(0xffffffffu, incl, o);
        if (lane >= o) incl += x;
    }
    __shared__ int ws[16];
    if (lane == 31) ws[wid] = incl;
    __syncthreads();
    if (wid == 0) {
        int s = (lane < 16) ? ws[lane] : 0;
        #pragma unroll
        for (int o = 1; o < 16; o <<= 1) {
            int x = __shfl_up_sync(0xffffffffu, s, o);
            if (lane >= o) s += x;
        }
        if (lane < 16) ws[lane] = s;
    }
    __syncthreads();
    int excl_local = incl - v + (wid ? ws[wid - 1] : 0);
    int block_total = ws[15];

    __shared__ int s_exclpref;
    if (wid == 0) {
        if (bid == 0) {
            if (lane == 0) {
                atomicExch(&g_scan_state[0],
                           ((unsigned long long)2 << 32) | (unsigned)block_total);
                s_exclpref = 0;
            }
        } else {
            if (lane == 0)
                atomicExch(&g_scan_state[bid],
                           ((unsigned long long)1 << 32) | (unsigned)block_total);
            int excl = 0;
            int lb = bid - 1;
            while (true) {
                int idx = lb - lane;
                unsigned long long s = (idx >= 0)
                    ? *(volatile unsigned long long*)&g_scan_state[idx]
                    : ((unsigned long long)2 << 32);
                int st = (int)(s >> 32);
                if (__all_sync(0xffffffffu, st != 0)) {
                    unsigned pre = __ballot_sync(0xffffffffu, st == 2);
                    unsigned val = (unsigned)s;
                    if (pre) {
                        int fp = __ffs(pre) - 1;
                        int c = (lane <= fp) ? (int)val : 0;
                        #pragma unroll
                        for (int o = 16; o; o >>= 1)
                            c += __shfl_down_sync(0xffffffffu, c, o);
                        excl += __shfl_sync(0xffffffffu, c, 0);
                        break;
                    } else {
                        int c = (int)val;
                        #pragma unroll
                        for (int o = 16; o; o >>= 1)
                            c += __shfl_down_sync(0xffffffffu, c, o);
                        excl += __shfl_sync(0xffffffffu, c, 0);
                        lb -= 32;
                    }
                }
            }
            if (lane == 0) {
                atomicExch(&g_scan_state[bid],
                           ((unsigned long long)2 << 32) | (unsigned)(excl + block_total));
                s_exclpref = excl;
            }
        }
    }
    __syncthreads();
    int off = excl_local + s_exclpref;
    if (i < n) {
        g_row_off[i] = off;
        g_cursor[i]  = off;
        if (i == n - 1) g_row_off[n] = off + v;
    }
}

// Stores BYTE offsets (src * 128 = src row start in g_h16).
__global__ void k_scatter(const int* __restrict__ src, const int* __restrict__ dst, int e) {
    int i = blockIdx.x * blockDim.x + threadIdx.x;
    if (i < e) {
        int p = atomicAdd(&g_cursor[dst[i]], 1);
        g_csr[p] = src[i] << 7;          // *128 bytes
    }
}

// ---------------------------------------------------------------- aggregate

__device__ __forceinline__ __half2 u2h(unsigned u) {
    return *reinterpret_cast<__half2*>(&u);
}
__device__ __forceinline__ unsigned h2u(__half2 h) {
    return *reinterpret_cast<unsigned*>(&h);
}

// 4 nodes per warp; 8 lanes per node; lane8 owns features [8*l8, 8*l8+7]
// (uint4 = 4 half2 = full 128B row across the 8 lanes).
// 8-edge windows: depth-2 fp16 pairwise tree, fp32 accumulate per quad.
__global__ void k_aggregate(int n) {
    int gtid = blockIdx.x * blockDim.x + threadIdx.x;
    int warp = gtid >> 5;
    int lane = gtid & 31;
    int g4  = lane >> 3;         // which of the 4 nodes
    int l8  = lane & 7;
    int node = warp * 4 + g4;
    if (node >= n) return;

    int beg = g_row_off[node];
    int end = g_row_off[node + 1];
    const char* hbase = (const char*)g_h16 + l8 * 16;

    float f0 = 0.f, f1 = 0.f, f2 = 0.f, f3 = 0.f;
    float f4 = 0.f, f5 = 0.f, f6 = 0.f, f7 = 0.f;
    int e = beg;
    for (; e + 8 <= end; e += 8) {
        int o0 = g_csr[e + 0], o1 = g_csr[e + 1], o2 = g_csr[e + 2], o3 = g_csr[e + 3];
        int o4 = g_csr[e + 4], o5 = g_csr[e + 5], o6 = g_csr[e + 6], o7 = g_csr[e + 7];
        uint4 v0 = *(const uint4*)(hbase + o0);
        uint4 v1 = *(const uint4*)(hbase + o1);
        uint4 v2 = *(const uint4*)(hbase + o2);
        uint4 v3 = *(const uint4*)(hbase + o3);
        uint4 v4 = *(const uint4*)(hbase + o4);
        uint4 v5 = *(const uint4*)(hbase + o5);
        uint4 v6 = *(const uint4*)(hbase + o6);
        uint4 v7 = *(const uint4*)(hbase + o7);
        // depth-1: pair adjacent edges (fp16)
        __half2 p01a = __hadd2(u2h(v0.x), u2h(v1.x));
        __half2 p01b = __hadd2(u2h(v0.y), u2h(v1.y));
        __half2 p01c = __hadd2(u2h(v0.z), u2h(v1.z));
        __half2 p01d = __hadd2(u2h(v0.w), u2h(v1.w));
        __half2 p23a = __hadd2(u2h(v2.x), u2h(v3.x));
        __half2 p23b = __hadd2(u2h(v2.y), u2h(v3.y));
        __half2 p23c = __hadd2(u2h(v2.z), u2h(v3.z));
        __half2 p23d = __hadd2(u2h(v2.w), u2h(v3.w));
        __half2 p45a = __hadd2(u2h(v4.x), u2h(v5.x));
        __half2 p45b = __hadd2(u2h(v4.y), u2h(v5.y));
        __half2 p45c = __hadd2(u2h(v4.z), u2h(v5.z));
        __half2 p45d = __hadd2(u2h(v4.w), u2h(v5.w));
        __half2 p67a = __hadd2(u2h(v6.x), u2h(v7.x));
        __half2 p67b = __hadd2(u2h(v6.y), u2h(v7.y));
        __half2 p67c = __hadd2(u2h(v6.z), u2h(v7.z));
        __half2 p67d = __hadd2(u2h(v6.w), u2h(v7.w));
        // depth-2: quad sums (fp16)
        __half2 q0a = __hadd2(p01a, p23a), q0b = __hadd2(p01b, p23b);
        __half2 q0c = __hadd2(p01c, p23c), q0d = __hadd2(p01d, p23d);
        __half2 q1a = __hadd2(p45a, p67a), q1b = __hadd2(p45b, p67b);
        __half2 q1c = __hadd2(p45c, p67c), q1d = __hadd2(p45d, p67d);
        // fp32 accumulate (2 quads)
        float2 a0 = __half22float2(q0a), a1 = __half22float2(q0b);
        float2 a2 = __half22float2(q0c), a3 = __half22float2(q0d);
        float2 b0 = __half22float2(q1a), b1 = __half22float2(q1b);
        float2 b2 = __half22float2(q1c), b3 = __half22float2(q1d);
        f0 += a0.x + b0.x;  f1 += a0.y + b0.y;
        f2 += a1.x + b1.x;  f3 += a1.y + b1.y;
        f4 += a2.x + b2.x;  f5 += a2.y + b2.y;
        f6 += a3.x + b3.x;  f7 += a3.y + b3.y;
    }
    for (; e < end; e++) {
        uint4 v = *(const uint4*)(hbase + g_csr[e]);
        float2 a0 = __half22float2(u2h(v.x));
        float2 a1 = __half22float2(u2h(v.y));
        float2 a2 = __half22float2(u2h(v.z));
        float2 a3 = __half22float2(u2h(v.w));
        f0 += a0.x; f1 += a0.y; f2 += a1.x; f3 += a1.y;
        f4 += a2.x; f5 += a2.y; f6 += a3.x; f7 += a3.y;
    }

    int deg = end - beg;
    float inv = 1.f / (float)(deg > 0 ? deg : 1);
    uint4 w;
    w.x = h2u(__float22half2_rn(make_float2(f0 * inv, f1 * inv)));
    w.y = h2u(__float22half2_rn(make_float2(f2 * inv, f3 * inv)));
    w.z = h2u(__float22half2_rn(make_float2(f4 * inv, f5 * inv)));
    w.w = h2u(__float22half2_rn(make_float2(f6 * inv, f7 * inv)));
    *(uint4*)((char*)g_a16 + (size_t)node * 128 + l8 * 16) = w;
}

// ---------------------------------------------------------------- transform

__device__ __forceinline__ void mma16816(float* d, const uint32_t* a,
                                         uint32_t b0, uint32_t b1) {
    asm volatile(
        "mma.sync.aligned.m16n8k16.row.col.f32.f16.f16.f32 "
        "{%0,%1,%2,%3}, {%4,%5,%6,%7}, {%8,%9}, {%0,%1,%2,%3};"
        : "+f"(d[0]), "+f"(d[1]), "+f"(d[2]), "+f"(d[3])
        : "r"(a[0]), "r"(a[1]), "r"(a[2]), "r"(a[3]), "r"(b0), "r"(b1));
}

// 256 threads per 128-node tile. Warp w (0..7) computes stripe [16w,16w+16).
// writeout: store fp32 result (layer 3 only). write16: store fp16 h for next layer.
__global__ void __launch_bounds__(256) k_transform(const float* __restrict__ Ws,
                                                   const float* __restrict__ Wn,
                                                   const float* __restrict__ b,
                                                   float* __restrict__ out,
                                                   int n, int leaky,
                                                   int write16, int writeout) {
    extern __shared__ __align__(16) __half sh[];
    __half (*sA)[PADK] = (__half(*)[PADK])sh;                // 128 rows
    __half (*sB)[PADK] = (__half(*)[PADK])(sh + 128 * PADK); // 64 rows
    __shared__ float sb[F];

    int t = threadIdx.x;
    int base = blockIdx.x * 128;

    for (int i = t; i < 64 * 32; i += 256) {
        int r = i >> 5, c4 = i & 31;
        int k0 = 4 * c4;
        float4 v = (k0 < 64) ? *(const float4*)(Ws + r * 64 + k0)
                             : *(const float4*)(Wn + r * 64 + (k0 - 64));
        *(__half2*)&sB[r][k0]     = __float22half2_rn(make_float2(v.x, v.y));
        *(__half2*)&sB[r][k0 + 2] = __float22half2_rn(make_float2(v.z, v.w));
    }
    for (int i = t; i < 128 * 16; i += 256) {
        int r = i >> 4, c8 = i & 15;
        int k0 = 8 * c8;
        int node = base + r;
        uint4 v = make_uint4(0u, 0u, 0u, 0u);
        if (node < n) {
            v = (k0 < 64)
              ? *(const uint4*)(g_h16 + (size_t)node * F + k0)
              : *(const uint4*)(g_a16 + (size_t)node * F + (k0 - 64));
        }
        *(uint4*)&sA[r][k0] = v;
    }
    if (t < F) sb[t] = b[t];
    __syncthreads();

    int lane = t & 31, w = t >> 5;
    int g  = lane >> 2;
    int tg = lane & 3;

    float acc[8][4];
    #pragma unroll
    for (int nt = 0; nt < 8; nt++)
        #pragma unroll
        for (int j = 0; j < 4; j++) acc[nt][j] = 0.f;

    int r0 = w * 16 + g;
    #pragma unroll
    for (int kt = 0; kt < 8; kt++) {
        int k0 = kt * 16 + tg * 2;
        uint32_t af[4];
        af[0] = *(const uint32_t*)&sA[r0][k0];
        af[1] = *(const uint32_t*)&sA[r0 + 8][k0];
        af[2] = *(const uint32_t*)&sA[r0][k0 + 8];
        af[3] = *(const uint32_t*)&sA[r0 + 8][k0 + 8];
        #pragma unroll
        for (int nt = 0; nt < 8; nt++) {
            uint32_t b0 = *(const uint32_t*)&sB[nt * 8 + g][k0];
            uint32_t b1 = *(const uint32_t*)&sB[nt * 8 + g][k0 + 8];
            mma16816(acc[nt], af, b0, b1);
        }
    }

    int node0 = base + r0;
    int node1 = node0 + 8;
    #pragma unroll
    for (int nt = 0; nt < 8; nt++) {
        int col = nt * 8 + tg * 2;
        float bx = sb[col], by = sb[col + 1];
        float2 v0, v1;
        v0.x = acc[nt][0] + bx;
        v0.y = acc[nt][1] + by;
        v1.x = acc[nt][2] + bx;
        v1.y = acc[nt][3] + by;
        if (leaky) {
            v0.x = v0.x >= 0.f ? v0.x : 0.01f * v0.x;
            v0.y = v0.y >= 0.f ? v0.y : 0.01f * v0.y;
            v1.x = v1.x >= 0.f ? v1.x : 0.01f * v1.x;
            v1.y = v1.y >= 0.f ? v1.y : 0.01f * v1.y;
        }
        if (node0 < n) {
            if (writeout)
                *(float2*)(out + (size_t)node0 * F + col) = v0;
            if (write16)
                *(__half2*)(g_h16 + (size_t)node0 * F + col) = __float22half2_rn(v0);
        }
        if (node1 < n) {
            if (writeout)
                *(float2*)(out + (size_t)node1 * F + col) = v1;
            if (write16)
                *(__half2*)(g_h16 + (size_t)node1 * F + col) = __float22half2_rn(v1);
        }
    }
}

// ---------------------------------------------------------------- launch

#define SMEM_TR ((128 + 64) * PADK * (int)sizeof(__half))   // 52224

extern "C" void kernel_launch(void* const* d_in, const int* in_sizes, int n_in,
                              void* d_out, int out_size) {
    const float* in_feat = (const float*)d_in[0];
    const int*   src     = (const int*)d_in[1];
    const int*   dst     = (const int*)d_in[2];
    const float* w_self1 = (const float*)d_in[3];
    const float* w_nei1  = (const float*)d_in[4];
    const float* b1      = (const float*)d_in[5];
    const float* w_self2 = (const float*)d_in[6];
    const float* w_nei2  = (const float*)d_in[7];
    const float* b2      = (const float*)d_in[8];
    const float* w_self3 = (const float*)d_in[9];
    const float* w_nei3  = (const float*)d_in[10];
    const float* b3      = (const float*)d_in[11];
    float* out = (float*)d_out;

    int n = in_sizes[0] / F;     // 100000
    int e = in_sizes[1];         // 1600000
    int nscan = (n + SCAN_BS - 1) / SCAN_BS;
    int n2 = n * F / 2;

    int* counts;
    cudaGetSymbolAddress((void**)&counts, g_counts);

    cudaFuncSetAttribute(k_transform, cudaFuncAttributeMaxDynamicSharedMemorySize,
                         SMEM_TR);

    // ---- CSR build + fp16 convert (fused) ----
    cudaMemsetAsync(counts, 0, (size_t)n * sizeof(int));
    int hc_items = (n2 > e) ? n2 : e;
    k_hist_cvt<<<(hc_items + 255) / 256, 256>>>(dst, e, in_feat, n2);
    k_scan_lookback<<<nscan, SCAN_BS>>>(n);
    k_scatter<<<(e + 255) / 256, 256>>>(src, dst, e);

    int agg_grid = ((n + 3) / 4 * 32 + 255) / 256;   // 4 nodes per warp
    int tr_grid  = (n + 127) / 128;

    k_aggregate<<<agg_grid, 256>>>(n);
    k_transform<<<tr_grid, 256, SMEM_TR>>>(w_self1, w_nei1, b1, out, n, 1, 1, 0);
    k_aggregate<<<agg_grid, 256>>>(n);
    k_transform<<<tr_grid, 256, SMEM_TR>>>(w_self2, w_nei2, b2, out, n, 1, 1, 0);
    k_aggregate<<<agg_grid, 256>>>(n);
    k_transform<<<tr_grid, 256, SMEM_TR>>>(w_self3, w_nei3, b3, out, n, 0, 0, 1);
}

// round 17
// speedup vs baseline: 2.8430x; 1.0120x over previous
#include <cuda_runtime.h>
#include <cuda_fp16.h>
#include <cstdint>

// GraphSAGE 3-layer, mean agg, N=100000, E=1600000, F=64.
// R17: aggregate 16/8/4/1 window cascade with fp16 tree (depth<=4, fp32 accum
//      per window) -> ~23% fewer instr/edge + cheaper tail; weights
//      pre-converted to fp16 once (in k_hist_cvt) so transform sB staging is
//      pure copies. Rest unchanged from R16 (170us).

#define F 64
#define NMAX 100000
#define EMAX 1600000
#define SCAN_BS 512
#define PADK 136          // half-elements per smem row (272B = 17*16)

__device__ int g_counts[NMAX];
__device__ int g_cursor[NMAX];
__device__ int g_row_off[NMAX + 1];
__device__ unsigned long long g_scan_state[256];
__device__ int g_csr[EMAX];                                // BYTE offsets (src*128)
__device__ __align__(16) __half g_h16[(size_t)NMAX * F];   // current layer input
__device__ __align__(16) __half g_a16[(size_t)NMAX * F];   // mean-neighbor agg
__device__ __align__(16) __half g_w16[3 * 64 * 128];       // [layer][row][k] fp16 [Ws|Wn]

// ------------------------------------------- CSR build (+ fp16 converts)

__global__ void k_hist_cvt(const int* __restrict__ dst, int e,
                           const float* __restrict__ in, int n2,
                           const float* __restrict__ ws1, const float* __restrict__ wn1,
                           const float* __restrict__ ws2, const float* __restrict__ wn2,
                           const float* __restrict__ ws3, const float* __restrict__ wn3) {
    int i = blockIdx.x * blockDim.x + threadIdx.x;
    if (i < 256) g_scan_state[i] = 0;
    if (i < n2) {
        float2 v = ((const float2*)in)[i];
        ((__half2*)g_h16)[i] = __float22half2_rn(v);
    }
    if (i < 3 * 64 * 64) {                 // weight half2 slots
        int layer = i >> 12;
        int rem = i & 4095;
        int r = rem >> 6;
        int k0 = (rem & 63) * 2;
        const float* Ws = layer == 0 ? ws1 : (layer == 1 ? ws2 : ws3);
        const float* Wn = layer == 0 ? wn1 : (layer == 1 ? wn2 : wn3);
        float2 v = (k0 < 64) ? *(const float2*)(Ws + r * 64 + k0)
                             : *(const float2*)(Wn + r * 64 + (k0 - 64));
        *(__half2*)&g_w16[layer * 8192 + r * 128 + k0] = __float22half2_rn(v);
    }
    if (i < e) atomicAdd(&g_counts[dst[i]], 1);
}

__global__ void k_scan_lookback(int n) {
    int bid = blockIdx.x;
    int t = threadIdx.x;
    int i = bid * SCAN_BS + t;
    int v = (i < n) ? g_counts[i] : 0;
    int lane = t & 31, wid = t >> 5;

    int incl = v;
    #pragma unroll
    for (int o = 1; o < 32; o <<= 1) {
        int x = __shfl_up_sync(0xffffffffu, incl, o);
        if (lane >= o) incl += x;
    }
    __shared__ int ws[16];
    if (lane == 31) ws[wid] = incl;
    __syncthreads();
    if (wid == 0) {
        int s = (lane < 16) ? ws[lane] : 0;
        #pragma unroll
        for (int o = 1; o < 16; o <<= 1) {
            int x = __shfl_up_sync(0xffffffffu, s, o);
            if (lane >= o) s += x;
        }
        if (lane < 16) ws[lane] = s;
    }
    __syncthreads();
    int excl_local = incl - v + (wid ? ws[wid - 1] : 0);
    int block_total = ws[15];

    __shared__ int s_exclpref;
    if (wid == 0) {
        if (bid == 0) {
            if (lane == 0) {
                atomicExch(&g_scan_state[0],
                           ((unsigned long long)2 << 32) | (unsigned)block_total);
                s_exclpref = 0;
            }
        } else {
            if (lane == 0)
                atomicExch(&g_scan_state[bid],
                           ((unsigned long long)1 << 32) | (unsigned)block_total);
            int excl = 0;
            int lb = bid - 1;
            while (true) {
                int idx = lb - lane;
                unsigned long long s = (idx >= 0)
                    ? *(volatile unsigned long long*)&g_scan_state[idx]
                    : ((unsigned long long)2 << 32);
                int st = (int)(s >> 32);
                if (__all_sync(0xffffffffu, st != 0)) {
                    unsigned pre = __ballot_sync(0xffffffffu, st == 2);
                    unsigned val = (unsigned)s;
                    if (pre) {
                        int fp = __ffs(pre) - 1;
                        int c = (lane <= fp) ? (int)val : 0;
                        #pragma unroll
                        for (int o = 16; o; o >>= 1)
                            c += __shfl_down_sync(0xffffffffu, c, o);
                        excl += __shfl_sync(0xffffffffu, c, 0);
                        break;
                    } else {
                        int c = (int)val;
                        #pragma unroll
                        for (int o = 16; o; o >>= 1)
                            c += __shfl_down_sync(0xffffffffu, c, o);
                        excl += __shfl_sync(0xffffffffu, c, 0);
                        lb -= 32;
                    }
                }
            }
            if (lane == 0) {
                atomicExch(&g_scan_state[bid],
                           ((unsigned long long)2 << 32) | (unsigned)(excl + block_total));
                s_exclpref = excl;
            }
        }
    }
    __syncthreads();
    int off = excl_local + s_exclpref;
    if (i < n) {
        g_row_off[i] = off;
        g_cursor[i]  = off;
        if (i == n - 1) g_row_off[n] = off + v;
    }
}

// Stores BYTE offsets (src * 128 = src row start in g_h16).
__global__ void k_scatter(const int* __restrict__ src, const int* __restrict__ dst, int e) {
    int i = blockIdx.x * blockDim.x + threadIdx.x;
    if (i < e) {
        int p = atomicAdd(&g_cursor[dst[i]], 1);
        g_csr[p] = src[i] << 7;          // *128 bytes
    }
}

// ---------------------------------------------------------------- aggregate

__device__ __forceinline__ __half2 u2h(unsigned u) {
    return *reinterpret_cast<__half2*>(&u);
}
__device__ __forceinline__ unsigned h2u(__half2 h) {
    return *reinterpret_cast<unsigned*>(&h);
}

// Sum 8 neighbor rows (this lane's 4 half2 chunk) into a depth-3 fp16 tree.
__device__ __forceinline__ void batch8(const char* hbase, int e, __half2 o[4]) {
    int o0 = g_csr[e + 0], o1 = g_csr[e + 1], o2 = g_csr[e + 2], o3 = g_csr[e + 3];
    int o4 = g_csr[e + 4], o5 = g_csr[e + 5], o6 = g_csr[e + 6], o7 = g_csr[e + 7];
    uint4 v0 = *(const uint4*)(hbase + o0);
    uint4 v1 = *(const uint4*)(hbase + o1);
    uint4 v2 = *(const uint4*)(hbase + o2);
    uint4 v3 = *(const uint4*)(hbase + o3);
    uint4 v4 = *(const uint4*)(hbase + o4);
    uint4 v5 = *(const uint4*)(hbase + o5);
    uint4 v6 = *(const uint4*)(hbase + o6);
    uint4 v7 = *(const uint4*)(hbase + o7);
    __half2 p0a = __hadd2(u2h(v0.x), u2h(v1.x)), p0b = __hadd2(u2h(v0.y), u2h(v1.y));
    __half2 p0c = __hadd2(u2h(v0.z), u2h(v1.z)), p0d = __hadd2(u2h(v0.w), u2h(v1.w));
    __half2 p1a = __hadd2(u2h(v2.x), u2h(v3.x)), p1b = __hadd2(u2h(v2.y), u2h(v3.y));
    __half2 p1c = __hadd2(u2h(v2.z), u2h(v3.z)), p1d = __hadd2(u2h(v2.w), u2h(v3.w));
    __half2 p2a = __hadd2(u2h(v4.x), u2h(v5.x)), p2b = __hadd2(u2h(v4.y), u2h(v5.y));
    __half2 p2c = __hadd2(u2h(v4.z), u2h(v5.z)), p2d = __hadd2(u2h(v4.w), u2h(v5.w));
    __half2 p3a = __hadd2(u2h(v6.x), u2h(v7.x)), p3b = __hadd2(u2h(v6.y), u2h(v7.y));
    __half2 p3c = __hadd2(u2h(v6.z), u2h(v7.z)), p3d = __hadd2(u2h(v6.w), u2h(v7.w));
    __half2 q0a = __hadd2(p0a, p1a), q0b = __hadd2(p0b, p1b);
    __half2 q0c = __hadd2(p0c, p1c), q0d = __hadd2(p0d, p1d);
    __half2 q1a = __hadd2(p2a, p3a), q1b = __hadd2(p2b, p3b);
    __half2 q1c = __hadd2(p2c, p3c), q1d = __hadd2(p2d, p3d);
    o[0] = __hadd2(q0a, q1a);
    o[1] = __hadd2(q0b, q1b);
    o[2] = __hadd2(q0c, q1c);
    o[3] = __hadd2(q0d, q1d);
}

// 4 nodes per warp; 8 lanes per node; lane8 owns features [8*l8, 8*l8+7].
// Window cascade 16/8/4/1; fp16 tree (<= depth 4), fp32 accumulate per window.
__global__ void k_aggregate(int n) {
    int gtid = blockIdx.x * blockDim.x + threadIdx.x;
    int warp = gtid >> 5;
    int lane = gtid & 31;
    int g4  = lane >> 3;
    int l8  = lane & 7;
    int node = warp * 4 + g4;
    if (node >= n) return;

    int beg = g_row_off[node];
    int end = g_row_off[node + 1];
    const char* hbase = (const char*)g_h16 + l8 * 16;

    float f0 = 0.f, f1 = 0.f, f2 = 0.f, f3 = 0.f;
    float f4 = 0.f, f5 = 0.f, f6 = 0.f, f7 = 0.f;
    int e = beg;
    for (; e + 16 <= end; e += 16) {
        __half2 oA[4], oB[4];
        batch8(hbase, e, oA);
        batch8(hbase, e + 8, oB);
        __half2 h0 = __hadd2(oA[0], oB[0]);
        __half2 h1 = __hadd2(oA[1], oB[1]);
        __half2 h2 = __hadd2(oA[2], oB[2]);
        __half2 h3 = __hadd2(oA[3], oB[3]);
        float2 a0 = __half22float2(h0), a1 = __half22float2(h1);
        float2 a2 = __half22float2(h2), a3 = __half22float2(h3);
        f0 += a0.x; f1 += a0.y; f2 += a1.x; f3 += a1.y;
        f4 += a2.x; f5 += a2.y; f6 += a3.x; f7 += a3.y;
    }
    if (e + 8 <= end) {
        __half2 o[4];
        batch8(hbase, e, o);
        float2 a0 = __half22float2(o[0]), a1 = __half22float2(o[1]);
        float2 a2 = __half22float2(o[2]), a3 = __half22float2(o[3]);
        f0 += a0.x; f1 += a0.y; f2 += a1.x; f3 += a1.y;
        f4 += a2.x; f5 += a2.y; f6 += a3.x; f7 += a3.y;
        e += 8;
    }
    if (e + 4 <= end) {
        int o0 = g_csr[e + 0], o1 = g_csr[e + 1], o2 = g_csr[e + 2], o3 = g_csr[e + 3];
        uint4 v0 = *(const uint4*)(hbase + o0);
        uint4 v1 = *(const uint4*)(hbase + o1);
        uint4 v2 = *(const uint4*)(hbase + o2);
        uint4 v3 = *(const uint4*)(hbase + o3);
        __half2 p0a = __hadd2(u2h(v0.x), u2h(v1.x)), p0b = __hadd2(u2h(v0.y), u2h(v1.y));
        __half2 p0c = __hadd2(u2h(v0.z), u2h(v1.z)), p0d = __hadd2(u2h(v0.w), u2h(v1.w));
        __half2 p1a = __hadd2(u2h(v2.x), u2h(v3.x)), p1b = __hadd2(u2h(v2.y), u2h(v3.y));
        __half2 p1c = __hadd2(u2h(v2.z), u2h(v3.z)), p1d = __hadd2(u2h(v2.w), u2h(v3.w));
        __half2 q0 = __hadd2(p0a, p1a), q1 = __hadd2(p0b, p1b);
        __half2 q2 = __hadd2(p0c, p1c), q3 = __hadd2(p0d, p1d);
        float2 a0 = __half22float2(q0), a1 = __half22float2(q1);
        float2 a2 = __half22float2(q2), a3 = __half22float2(q3);
        f0 += a0.x; f1 += a0.y; f2 += a1.x; f3 += a1.y;
        f4 += a2.x; f5 += a2.y; f6 += a3.x; f7 += a3.y;
        e += 4;
    }
    for (; e < end; e++) {
        uint4 v = *(const uint4*)(hbase + g_csr[e]);
        float2 a0 = __half22float2(u2h(v.x));
        float2 a1 = __half22float2(u2h(v.y));
        float2 a2 = __half22float2(u2h(v.z));
        float2 a3 = __half22float2(u2h(v.w));
        f0 += a0.x; f1 += a0.y; f2 += a1.x; f3 += a1.y;
        f4 += a2.x; f5 += a2.y; f6 += a3.x; f7 += a3.y;
    }

    int deg = end - beg;
    float inv = 1.f / (float)(deg > 0 ? deg : 1);
    uint4 w;
    w.x = h2u(__float22half2_rn(make_float2(f0 * inv, f1 * inv)));
    w.y = h2u(__float22half2_rn(make_float2(f2 * inv, f3 * inv)));
    w.z = h2u(__float22half2_rn(make_float2(f4 * inv, f5 * inv)));
    w.w = h2u(__float22half2_rn(make_float2(f6 * inv, f7 * inv)));
    *(uint4*)((char*)g_a16 + (size_t)node * 128 + l8 * 16) = w;
}

// ---------------------------------------------------------------- transform

__device__ __forceinline__ void mma16816(float* d, const uint32_t* a,
                                         uint32_t b0, uint32_t b1) {
    asm volatile(
        "mma.sync.aligned.m16n8k16.row.col.f32.f16.f16.f32 "
        "{%0,%1,%2,%3}, {%4,%5,%6,%7}, {%8,%9}, {%0,%1,%2,%3};"
        : "+f"(d[0]), "+f"(d[1]), "+f"(d[2]), "+f"(d[3])
        : "r"(a[0]), "r"(a[1]), "r"(a[2]), "r"(a[3]), "r"(b0), "r"(b1));
}

// 256 threads per 128-node tile. Warp w (0..7) computes stripe [16w,16w+16).
__global__ void __launch_bounds__(256) k_transform(int layer,
                                                   const float* __restrict__ b,
                                                   float* __restrict__ out,
                                                   int n, int leaky,
                                                   int write16, int writeout) {
    extern __shared__ __align__(16) __half sh[];
    __half (*sA)[PADK] = (__half(*)[PADK])sh;                // 128 rows
    __half (*sB)[PADK] = (__half(*)[PADK])(sh + 128 * PADK); // 64 rows
    __shared__ float sb[F];

    int t = threadIdx.x;
    int base = blockIdx.x * 128;
    const __half* Wf = g_w16 + layer * 8192;

    // stage B: pure fp16 copies (uint4 = 8 halfs)
    for (int i = t; i < 64 * 16; i += 256) {
        int r = i >> 4, c8 = i & 15;
        int k0 = 8 * c8;
        *(uint4*)&sB[r][k0] = *(const uint4*)(Wf + r * 128 + k0);
    }
    // stage A: fp16 copies from h/agg buffers
    for (int i = t; i < 128 * 16; i += 256) {
        int r = i >> 4, c8 = i & 15;
        int k0 = 8 * c8;
        int node = base + r;
        uint4 v = make_uint4(0u, 0u, 0u, 0u);
        if (node < n) {
            v = (k0 < 64)
              ? *(const uint4*)(g_h16 + (size_t)node * F + k0)
              : *(const uint4*)(g_a16 + (size_t)node * F + (k0 - 64));
        }
        *(uint4*)&sA[r][k0] = v;
    }
    if (t < F) sb[t] = b[t];
    __syncthreads();

    int lane = t & 31, w = t >> 5;
    int g  = lane >> 2;
    int tg = lane & 3;

    float acc[8][4];
    #pragma unroll
    for (int nt = 0; nt < 8; nt++)
        #pragma unroll
        for (int j = 0; j < 4; j++) acc[nt][j] = 0.f;

    int r0 = w * 16 + g;
    #pragma unroll
    for (int kt = 0; kt < 8; kt++) {
        int k0 = kt * 16 + tg * 2;
        uint32_t af[4];
        af[0] = *(const uint32_t*)&sA[r0][k0];
        af[1] = *(const uint32_t*)&sA[r0 + 8][k0];
        af[2] = *(const uint32_t*)&sA[r0][k0 + 8];
        af[3] = *(const uint32_t*)&sA[r0 + 8][k0 + 8];
        #pragma unroll
        for (int nt = 0; nt < 8; nt++) {
            uint32_t b0 = *(const uint32_t*)&sB[nt * 8 + g][k0];
            uint32_t b1 = *(const uint32_t*)&sB[nt * 8 + g][k0 + 8];
            mma16816(acc[nt], af, b0, b1);
        }
    }

    int node0 = base + r0;
    int node1 = node0 + 8;
    #pragma unroll
    for (int nt = 0; nt < 8; nt++) {
        int col = nt * 8 + tg * 2;
        float bx = sb[col], by = sb[col + 1];
        float2 v0, v1;
        v0.x = acc[nt][0] + bx;
        v0.y = acc[nt][1] + by;
        v1.x = acc[nt][2] + bx;
        v1.y = acc[nt][3] + by;
        if (leaky) {
            v0.x = v0.x >= 0.f ? v0.x : 0.01f * v0.x;
            v0.y = v0.y >= 0.f ? v0.y : 0.01f * v0.y;
            v1.x = v1.x >= 0.f ? v1.x : 0.01f * v1.x;
            v1.y = v1.y >= 0.f ? v1.y : 0.01f * v1.y;
        }
        if (node0 < n) {
            if (writeout)
                *(float2*)(out + (size_t)node0 * F + col) = v0;
            if (write16)
                *(__half2*)(g_h16 + (size_t)node0 * F + col) = __float22half2_rn(v0);
        }
        if (node1 < n) {
            if (writeout)
                *(float2*)(out + (size_t)node1 * F + col) = v1;
            if (write16)
                *(__half2*)(g_h16 + (size_t)node1 * F + col) = __float22half2_rn(v1);
        }
    }
}

// ---------------------------------------------------------------- launch

#define SMEM_TR ((128 + 64) * PADK * (int)sizeof(__half))   // 52224

extern "C" void kernel_launch(void* const* d_in, const int* in_sizes, int n_in,
                              void* d_out, int out_size) {
    const float* in_feat = (const float*)d_in[0];
    const int*   src     = (const int*)d_in[1];
    const int*   dst     = (const int*)d_in[2];
    const float* w_self1 = (const float*)d_in[3];
    const float* w_nei1  = (const float*)d_in[4];
    const float* b1      = (const float*)d_in[5];
    const float* w_self2 = (const float*)d_in[6];
    const float* w_nei2  = (const float*)d_in[7];
    const float* b2      = (const float*)d_in[8];
    const float* w_self3 = (const float*)d_in[9];
    const float* w_nei3  = (const float*)d_in[10];
    const float* b3      = (const float*)d_in[11];
    float* out = (float*)d_out;

    int n = in_sizes[0] / F;     // 100000
    int e = in_sizes[1];         // 1600000
    int nscan = (n + SCAN_BS - 1) / SCAN_BS;
    int n2 = n * F / 2;

    int* counts;
    cudaGetSymbolAddress((void**)&counts, g_counts);

    cudaFuncSetAttribute(k_transform, cudaFuncAttributeMaxDynamicSharedMemorySize,
                         SMEM_TR);

    // ---- CSR build + fp16 converts (fused) ----
    cudaMemsetAsync(counts, 0, (size_t)n * sizeof(int));
    int hc_items = (n2 > e) ? n2 : e;
    k_hist_cvt<<<(hc_items + 255) / 256, 256>>>(dst, e, in_feat, n2,
                                                w_self1, w_nei1, w_self2, w_nei2,
                                                w_self3, w_nei3);
    k_scan_lookback<<<nscan, SCAN_BS>>>(n);
    k_scatter<<<(e + 255) / 256, 256>>>(src, dst, e);

    int agg_grid = ((n + 3) / 4 * 32 + 255) / 256;   // 4 nodes per warp
    int tr_grid  = (n + 127) / 128;

    k_aggregate<<<agg_grid, 256>>>(n);
    k_transform<<<tr_grid, 256, SMEM_TR>>>(0, b1, out, n, 1, 1, 0);
    k_aggregate<<<agg_grid, 256>>>(n);
    k_transform<<<tr_grid, 256, SMEM_TR>>>(1, b2, out, n, 1, 1, 0);
    k_aggregate<<<agg_grid, 256>>>(n);
    k_transform<<<tr_grid, 256, SMEM_TR>>>(2, b3, out, n, 0, 0, 1);
}